// round 2
// baseline (speedup 1.0000x reference)
#include <cuda_runtime.h>
#include <cstdint>

// ---------------------------------------------------------------------------
// MultiHeadAttention: B=4, S=2048, D=1024, H=16, Dk=64, fp32.
// Round 1: fix attention tile loads (R0 loaded only 1/4 of each KV tile).
// ---------------------------------------------------------------------------

#define BATCH 4
#define SEQ   2048
#define DMODEL 1024
#define HEADS 16
#define DK    64
#define MROWS (BATCH * SEQ)          // 8192

// Scratch (device globals; no allocation allowed)
__device__ __align__(128) float g_q[BATCH * HEADS * SEQ * DK];
__device__ __align__(128) float g_k[BATCH * HEADS * SEQ * DK];
__device__ __align__(128) float g_v[BATCH * HEADS * SEQ * DK];
__device__ __align__(128) float g_ao[MROWS * DMODEL];

// ---------------------------------------------------------------------------
// Tiled GEMM: out = A[M,K] @ W[K,N] + bias[N]
// mode 0: scatter output to [B,H,S,Dk] layout (QKV projections)
// mode 1: row-major [M,N] output (final projection)
// BM=BN=64, BK=16, 256 threads, 4x4 per thread.
// ---------------------------------------------------------------------------
__global__ __launch_bounds__(256) void gemm_bias_kernel(
    const float* __restrict__ A, const float* __restrict__ W,
    const float* __restrict__ bias, float* __restrict__ out,
    int M, int N, int K, int mode)
{
    __shared__ float AsT[16][64];   // k-major A tile
    __shared__ float Bs[16][64];    // B tile

    const int tid = threadIdx.x;
    const int tx = tid & 15;        // 0..15 -> 4 cols each
    const int ty = tid >> 4;        // 0..15 -> 4 rows each
    const int m0 = blockIdx.y * 64;
    const int n0 = blockIdx.x * 64;

    float acc[4][4] = {};

    const int a_row = tid >> 2;     // 0..63
    const int a_c4  = tid & 3;      // 0..3 (float4 within 16 k-cols)
    const int b_row = tid >> 4;     // 0..15
    const int b_c4  = tid & 15;     // 0..15 (float4 within 64 n-cols)

    for (int k0 = 0; k0 < K; k0 += 16) {
        // Load A tile 64x16, store transposed
        float4 av = *(const float4*)(A + (size_t)(m0 + a_row) * K + k0 + a_c4 * 4);
        AsT[a_c4 * 4 + 0][a_row] = av.x;
        AsT[a_c4 * 4 + 1][a_row] = av.y;
        AsT[a_c4 * 4 + 2][a_row] = av.z;
        AsT[a_c4 * 4 + 3][a_row] = av.w;
        // Load B tile 16x64
        float4 bv = *(const float4*)(W + (size_t)(k0 + b_row) * N + n0 + b_c4 * 4);
        *(float4*)&Bs[b_row][b_c4 * 4] = bv;
        __syncthreads();

        #pragma unroll
        for (int kk = 0; kk < 16; kk++) {
            float a[4], b[4];
            #pragma unroll
            for (int i = 0; i < 4; i++) a[i] = AsT[kk][ty * 4 + i];
            #pragma unroll
            for (int j = 0; j < 4; j++) b[j] = Bs[kk][tx * 4 + j];
            #pragma unroll
            for (int i = 0; i < 4; i++)
                #pragma unroll
                for (int j = 0; j < 4; j++)
                    acc[i][j] = fmaf(a[i], b[j], acc[i][j]);
        }
        __syncthreads();
    }

    // Epilogue
    #pragma unroll
    for (int i = 0; i < 4; i++) {
        int m = m0 + ty * 4 + i;
        #pragma unroll
        for (int j = 0; j < 4; j++) {
            int n = n0 + tx * 4 + j;
            float val = acc[i][j] + bias[n];
            if (mode == 0) {
                int b = m >> 11;          // m / 2048
                int s = m & 2047;
                int h = n >> 6;           // n / 64
                int d = n & 63;
                out[(((size_t)b * HEADS + h) * SEQ + s) * DK + d] = val;
            } else {
                out[(size_t)m * N + n] = val;
            }
        }
    }
}

// ---------------------------------------------------------------------------
// Flash attention: per CTA one (b,h, 64-row q tile). KV tiles of 64.
// 256 threads (16x16), each thread owns 4x4 of the 64x64 score tile and
// 4x4 of the 64x64 output tile. Online softmax with shfl row reductions.
// Output written in [B,S,H*Dk] layout into g_ao.
// QsT/KsT padded to stride 65 (transposed scalar stores otherwise 16-way
// bank-conflict).
// ---------------------------------------------------------------------------
#define QK_STRIDE 65

__global__ __launch_bounds__(256) void attn_kernel(
    const float* __restrict__ Q, const float* __restrict__ K,
    const float* __restrict__ V, float* __restrict__ out)
{
    extern __shared__ float sm[];
    float* QsT = sm;                           // [64 d][65]
    float* KsT = sm + 64 * QK_STRIDE;          // [64 d][65]
    float* Vs  = sm + 2 * 64 * QK_STRIDE;      // [64 k][64 d]
    float* Ps  = sm + 2 * 64 * QK_STRIDE + 64 * 64;  // [64 q][65]

    const int tid = threadIdx.x;
    const int tx = tid & 15;
    const int ty = tid >> 4;
    const int qt = blockIdx.x;       // 0..31
    const int bh = blockIdx.y;       // 0..63
    const int bb = bh >> 4;          // batch
    const int hh = bh & 15;          // head

    const float* Qp = Q + ((size_t)bh * SEQ + qt * 64) * DK;
    const float* Kp = K + (size_t)bh * SEQ * DK;
    const float* Vp = V + (size_t)bh * SEQ * DK;

    // Load full 64x64 Q tile transposed, pre-scaled by 1/sqrt(Dk).
    // 4096 floats = 1024 float4 = 4 per thread.
    {
        const float sc = 0.125f;
        #pragma unroll
        for (int it = 0; it < 4; it++) {
            int idx = tid + it * 256;    // 0..1023
            int row = idx >> 4;          // 0..63
            int cg  = idx & 15;          // 0..15 (float4 column group)
            float4 v = *(const float4*)(Qp + (size_t)row * DK + cg * 4);
            QsT[(cg * 4 + 0) * QK_STRIDE + row] = v.x * sc;
            QsT[(cg * 4 + 1) * QK_STRIDE + row] = v.y * sc;
            QsT[(cg * 4 + 2) * QK_STRIDE + row] = v.z * sc;
            QsT[(cg * 4 + 3) * QK_STRIDE + row] = v.w * sc;
        }
    }

    float m_i[4], l_i[4], O[4][4];
    #pragma unroll
    for (int i = 0; i < 4; i++) {
        m_i[i] = -1e30f; l_i[i] = 0.f;
        #pragma unroll
        for (int j = 0; j < 4; j++) O[i][j] = 0.f;
    }

    for (int kt = 0; kt < SEQ / 64; kt++) {
        __syncthreads();   // protect K/V from previous iteration's readers
        #pragma unroll
        for (int it = 0; it < 4; it++) {
            int idx = tid + it * 256;
            int row = idx >> 4;
            int cg  = idx & 15;
            float4 v = *(const float4*)(Kp + (size_t)(kt * 64 + row) * DK + cg * 4);
            KsT[(cg * 4 + 0) * QK_STRIDE + row] = v.x;
            KsT[(cg * 4 + 1) * QK_STRIDE + row] = v.y;
            KsT[(cg * 4 + 2) * QK_STRIDE + row] = v.z;
            KsT[(cg * 4 + 3) * QK_STRIDE + row] = v.w;
            float4 w = *(const float4*)(Vp + (size_t)(kt * 64 + row) * DK + cg * 4);
            *(float4*)&Vs[row * 64 + cg * 4] = w;
        }
        __syncthreads();

        // S = Q K^T (scaled)
        float s[4][4] = {};
        #pragma unroll
        for (int kk = 0; kk < 64; kk++) {
            float a[4], b[4];
            #pragma unroll
            for (int i = 0; i < 4; i++) a[i] = QsT[kk * QK_STRIDE + ty * 4 + i];
            #pragma unroll
            for (int j = 0; j < 4; j++) b[j] = KsT[kk * QK_STRIDE + tx * 4 + j];
            #pragma unroll
            for (int i = 0; i < 4; i++)
                #pragma unroll
                for (int j = 0; j < 4; j++)
                    s[i][j] = fmaf(a[i], b[j], s[i][j]);
        }

        // Online softmax per q-row (16 lanes of same ty share a row)
        #pragma unroll
        for (int i = 0; i < 4; i++) {
            float rm = fmaxf(fmaxf(s[i][0], s[i][1]), fmaxf(s[i][2], s[i][3]));
            #pragma unroll
            for (int off = 8; off > 0; off >>= 1)
                rm = fmaxf(rm, __shfl_xor_sync(0xffffffffu, rm, off));
            float mn = fmaxf(m_i[i], rm);
            float corr = __expf(m_i[i] - mn);
            float rs = 0.f;
            #pragma unroll
            for (int j = 0; j < 4; j++) {
                float p = __expf(s[i][j] - mn);
                s[i][j] = p;
                rs += p;
            }
            #pragma unroll
            for (int off = 8; off > 0; off >>= 1)
                rs += __shfl_xor_sync(0xffffffffu, rs, off);
            l_i[i] = l_i[i] * corr + rs;
            m_i[i] = mn;
            #pragma unroll
            for (int j = 0; j < 4; j++) {
                O[i][j] *= corr;
                Ps[(ty * 4 + i) * 65 + tx * 4 + j] = s[i][j];
            }
        }
        __syncthreads();

        // O += P @ V
        #pragma unroll
        for (int kk = 0; kk < 64; kk++) {
            float p[4], v[4];
            #pragma unroll
            for (int i = 0; i < 4; i++) p[i] = Ps[(ty * 4 + i) * 65 + kk];
            #pragma unroll
            for (int j = 0; j < 4; j++) v[j] = Vs[kk * 64 + tx * 4 + j];
            #pragma unroll
            for (int i = 0; i < 4; i++)
                #pragma unroll
                for (int j = 0; j < 4; j++)
                    O[i][j] = fmaf(p[i], v[j], O[i][j]);
        }
    }

    // Write to [B,S,H*Dk]
    #pragma unroll
    for (int i = 0; i < 4; i++) {
        float inv_l = 1.0f / l_i[i];
        int srow = qt * 64 + ty * 4 + i;
        #pragma unroll
        for (int j = 0; j < 4; j++) {
            int d = tx * 4 + j;
            out[((size_t)bb * SEQ + srow) * DMODEL + hh * DK + d] = O[i][j] * inv_l;
        }
    }
}

// ---------------------------------------------------------------------------
// Launch
// ---------------------------------------------------------------------------
extern "C" void kernel_launch(void* const* d_in, const int* in_sizes, int n_in,
                              void* d_out, int out_size)
{
    const float* x  = (const float*)d_in[0];
    const float* wq = (const float*)d_in[1];
    const float* bq = (const float*)d_in[2];
    const float* wk = (const float*)d_in[3];
    const float* bk = (const float*)d_in[4];
    const float* wv = (const float*)d_in[5];
    const float* bv = (const float*)d_in[6];
    const float* wo = (const float*)d_in[7];
    const float* bo = (const float*)d_in[8];
    float* out = (float*)d_out;

    float *q_ptr, *k_ptr, *v_ptr, *ao_ptr;
    cudaGetSymbolAddress((void**)&q_ptr,  g_q);
    cudaGetSymbolAddress((void**)&k_ptr,  g_k);
    cudaGetSymbolAddress((void**)&v_ptr,  g_v);
    cudaGetSymbolAddress((void**)&ao_ptr, g_ao);

    const int attn_smem = (2 * 64 * QK_STRIDE + 64 * 64 + 64 * 65) * (int)sizeof(float);
    cudaFuncSetAttribute(attn_kernel,
                         cudaFuncAttributeMaxDynamicSharedMemorySize, attn_smem);

    dim3 gemm_grid(DMODEL / 64, MROWS / 64);   // (16, 128)

    gemm_bias_kernel<<<gemm_grid, 256>>>(x, wq, bq, q_ptr, MROWS, DMODEL, DMODEL, 0);
    gemm_bias_kernel<<<gemm_grid, 256>>>(x, wk, bk, k_ptr, MROWS, DMODEL, DMODEL, 0);
    gemm_bias_kernel<<<gemm_grid, 256>>>(x, wv, bv, v_ptr, MROWS, DMODEL, DMODEL, 0);

    dim3 attn_grid(SEQ / 64, BATCH * HEADS);   // (32, 64)
    attn_kernel<<<attn_grid, 256, attn_smem>>>(q_ptr, k_ptr, v_ptr, ao_ptr);

    gemm_bias_kernel<<<gemm_grid, 256>>>(ao_ptr, wo, bo, out, MROWS, DMODEL, DMODEL, 1);
}

// round 4
// speedup vs baseline: 1.4762x; 1.4762x over previous
#include <cuda_runtime.h>
#include <cuda_bf16.h>
#include <cstdint>

// ---------------------------------------------------------------------------
// MultiHeadAttention: B=4, S=2048, D=1024, H=16, Dk=64, fp32.
// Round 4: projections via mma.sync bf16 (2-term split, fp32 accum).
//          tcgen05 unavailable (harness targets sm_103 without 'a').
// ---------------------------------------------------------------------------

#define BATCH 4
#define SEQ   2048
#define DMODEL 1024
#define HEADS 16
#define DK    64
#define MROWS (BATCH * SEQ)          // 8192
#define WSZ   (DMODEL * DMODEL)

// ---------------- scratch ----------------------------------------------------
__device__ __align__(128) float g_q[BATCH * HEADS * SEQ * DK];
__device__ __align__(128) float g_k[BATCH * HEADS * SEQ * DK];
__device__ __align__(128) float g_v[BATCH * HEADS * SEQ * DK];
__device__ __align__(128) float g_ao[MROWS * DMODEL];
__device__ __align__(128) __nv_bfloat16 g_xhi[MROWS * DMODEL];
__device__ __align__(128) __nv_bfloat16 g_xlo[MROWS * DMODEL];
__device__ __align__(128) __nv_bfloat16 g_aohi[MROWS * DMODEL];
__device__ __align__(128) __nv_bfloat16 g_aolo[MROWS * DMODEL];
__device__ __align__(128) __nv_bfloat16 g_wthi[4 * WSZ];   // [N,K] transposed
__device__ __align__(128) __nv_bfloat16 g_wtlo[4 * WSZ];

// ---------------- PTX helpers ------------------------------------------------
__device__ __forceinline__ uint32_t smem_u32(const void* p) {
    uint32_t a;
    asm("{ .reg .u64 t; cvta.to.shared.u64 t, %1; cvt.u32.u64 %0, t; }"
        : "=r"(a) : "l"(p));
    return a;
}
__device__ __forceinline__ void ldsm_x4(uint32_t* r, uint32_t addr) {
    asm volatile("ldmatrix.sync.aligned.m8n8.x4.shared.b16 {%0,%1,%2,%3}, [%4];"
        : "=r"(r[0]), "=r"(r[1]), "=r"(r[2]), "=r"(r[3]) : "r"(addr));
}
__device__ __forceinline__ void ldsm_x2(uint32_t* r, uint32_t addr) {
    asm volatile("ldmatrix.sync.aligned.m8n8.x2.shared.b16 {%0,%1}, [%2];"
        : "=r"(r[0]), "=r"(r[1]) : "r"(addr));
}
__device__ __forceinline__ void mma_bf16(float* c, const uint32_t* a, const uint32_t* b) {
    asm volatile(
        "mma.sync.aligned.m16n8k16.row.col.f32.bf16.bf16.f32 "
        "{%0,%1,%2,%3}, {%4,%5,%6,%7}, {%8,%9}, {%0,%1,%2,%3};"
        : "+f"(c[0]), "+f"(c[1]), "+f"(c[2]), "+f"(c[3])
        : "r"(a[0]), "r"(a[1]), "r"(a[2]), "r"(a[3]), "r"(b[0]), "r"(b[1]));
}
#define CP_ASYNC16(dst, src) \
    asm volatile("cp.async.cg.shared.global [%0], [%1], 16;" \
                 :: "r"(dst), "l"(src))
#define CP_COMMIT() asm volatile("cp.async.commit_group;" ::: "memory")
#define CP_WAIT(n)  asm volatile("cp.async.wait_group %0;" :: "n"(n) : "memory")

// ---------------- split fp32 -> bf16 hi/lo -----------------------------------
__global__ __launch_bounds__(256) void split_kernel(
    const float* __restrict__ in, __nv_bfloat16* __restrict__ hi,
    __nv_bfloat16* __restrict__ lo, int n4)
{
    int i = blockIdx.x * 256 + threadIdx.x;
    if (i >= n4) return;
    float4 v = ((const float4*)in)[i];
    __nv_bfloat16 h[4], l[4];
    float f[4] = {v.x, v.y, v.z, v.w};
    #pragma unroll
    for (int j = 0; j < 4; j++) {
        h[j] = __float2bfloat16(f[j]);
        l[j] = __float2bfloat16(f[j] - __bfloat162float(h[j]));
    }
    ((uint2*)hi)[i] = *(uint2*)h;
    ((uint2*)lo)[i] = *(uint2*)l;
}

// ---------------- transpose+split: W[K,N] fp32 -> Wt[N,K] bf16 hi/lo ---------
__global__ __launch_bounds__(256) void wtrans_kernel(
    const float* __restrict__ W, __nv_bfloat16* __restrict__ Th,
    __nv_bfloat16* __restrict__ Tl)
{
    __shared__ float tile[32][33];
    const int n0 = blockIdx.x * 32, k0 = blockIdx.y * 32;
    const int tx = threadIdx.x & 31, ty = threadIdx.x >> 5;   // 32 x 8
    #pragma unroll
    for (int r = 0; r < 4; r++)
        tile[ty + 8 * r][tx] = W[(size_t)(k0 + ty + 8 * r) * DMODEL + n0 + tx];
    __syncthreads();
    #pragma unroll
    for (int r = 0; r < 4; r++) {
        int n = n0 + ty + 8 * r, k = k0 + tx;
        float v = tile[tx][ty + 8 * r];
        __nv_bfloat16 h = __float2bfloat16(v);
        __nv_bfloat16 l = __float2bfloat16(v - __bfloat162float(h));
        Th[(size_t)n * DMODEL + k] = h;
        Tl[(size_t)n * DMODEL + k] = l;
    }
}

// ---------------- mma.sync GEMM ----------------------------------------------
// out[M,N] = (Ah+Al)[M,K] @ ((Bh+Bl)[N,K])^T + bias, 2-term split.
// CTA tile 128x128, 8 warps (warp tile 64m x 32n), BK=64, 2-stage cp.async.
#define BK 64
#define NCHUNK (DMODEL / BK)     // 16
#define ROWB 144                  // padded row stride in bytes (72 bf16)
#define TILE_BYTES (128 * ROWB)   // 18432
#define STAGE_BYTES (4 * TILE_BYTES)
#define GEMM_SMEM (2 * STAGE_BYTES)   // 147456

__global__ __launch_bounds__(256, 1) void gemm_mma(
    const __nv_bfloat16* __restrict__ Ah, const __nv_bfloat16* __restrict__ Al,
    const __nv_bfloat16* __restrict__ Bh, const __nv_bfloat16* __restrict__ Bl,
    const float* __restrict__ bias, float* __restrict__ out, int mode)
{
    extern __shared__ char smem[];
    const uint32_t sbase = smem_u32(smem);
    const int tid = threadIdx.x;
    const int wid = tid >> 5, lane = tid & 31;
    const int n0 = blockIdx.x * 128;
    const int m0 = blockIdx.y * 128;

    const int warp_m = (wid & 1) * 64;
    const int warp_n = (wid >> 1) * 32;

    const __nv_bfloat16* gp[4] = {
        Ah + (size_t)m0 * DMODEL, Al + (size_t)m0 * DMODEL,
        Bh + (size_t)n0 * DMODEL, Bl + (size_t)n0 * DMODEL };

    // async-load one K-chunk into stage s
    auto load_stage = [&](int s, int c) {
        const int k0 = c * BK;
        const uint32_t stage = sbase + s * STAGE_BYTES;
        #pragma unroll
        for (int t = 0; t < 4; t++) {
            #pragma unroll
            for (int i = 0; i < 4; i++) {
                int idx = tid + i * 256;        // 0..1023
                int row = idx >> 3;             // 0..127
                int ch  = idx & 7;              // 0..7 (16B chunks of 128B row)
                uint32_t dst = stage + t * TILE_BYTES + row * ROWB + ch * 16;
                const __nv_bfloat16* src = gp[t] + (size_t)row * DMODEL + k0 + ch * 8;
                CP_ASYNC16(dst, src);
            }
        }
    };

    float acc[4][4][4];
    #pragma unroll
    for (int i = 0; i < 4; i++)
        #pragma unroll
        for (int j = 0; j < 4; j++)
            #pragma unroll
            for (int q = 0; q < 4; q++) acc[i][j][q] = 0.f;

    load_stage(0, 0); CP_COMMIT();
    load_stage(1, 1); CP_COMMIT();

    // ldmatrix lane addressing (within a tile)
    const int a_row = lane & 15;
    const int a_kb  = (lane & 16) ? 16 : 0;     // byte offset of k+8 half
    const int b_row = lane & 7;
    const int b_kb  = (lane & 8) ? 16 : 0;

    for (int c = 0; c < NCHUNK; c++) {
        if (c + 1 < NCHUNK) { CP_WAIT(1); } else { CP_WAIT(0); }
        __syncthreads();

        const uint32_t stage = sbase + (c & 1) * STAGE_BYTES;
        const uint32_t tAh = stage;
        const uint32_t tAl = stage + TILE_BYTES;
        const uint32_t tBh = stage + 2 * TILE_BYTES;
        const uint32_t tBl = stage + 3 * TILE_BYTES;

        #pragma unroll
        for (int ks = 0; ks < BK / 16; ks++) {
            uint32_t ah[4][4], al[4][4], bh[4][2], bl[4][2];
            #pragma unroll
            for (int mf = 0; mf < 4; mf++) {
                uint32_t off = (uint32_t)((warp_m + mf * 16 + a_row) * ROWB
                                          + ks * 32 + a_kb);
                ldsm_x4(ah[mf], tAh + off);
                ldsm_x4(al[mf], tAl + off);
            }
            #pragma unroll
            for (int nf = 0; nf < 4; nf++) {
                uint32_t off = (uint32_t)((warp_n + nf * 8 + b_row) * ROWB
                                          + ks * 32 + b_kb);
                ldsm_x2(bh[nf], tBh + off);
                ldsm_x2(bl[nf], tBl + off);
            }
            #pragma unroll
            for (int mf = 0; mf < 4; mf++)
                #pragma unroll
                for (int nf = 0; nf < 4; nf++) {
                    mma_bf16(acc[mf][nf], ah[mf], bh[nf]);
                    mma_bf16(acc[mf][nf], ah[mf], bl[nf]);
                    mma_bf16(acc[mf][nf], al[mf], bh[nf]);
                }
        }
        __syncthreads();
        if (c + 2 < NCHUNK) { load_stage(c & 1, c + 2); CP_COMMIT(); }
    }

    // Epilogue: c-frag thread layout (m = lane/4 [+8], n = (lane%4)*2 [+1])
    #pragma unroll
    for (int mf = 0; mf < 4; mf++) {
        const int mA = m0 + warp_m + mf * 16 + (lane >> 2);
        #pragma unroll
        for (int nf = 0; nf < 4; nf++) {
            const int n = n0 + warp_n + nf * 8 + (lane & 3) * 2;
            const float b0 = bias[n], b1 = bias[n + 1];
            float2 v0 = { acc[mf][nf][0] + b0, acc[mf][nf][1] + b1 };
            float2 v1 = { acc[mf][nf][2] + b0, acc[mf][nf][3] + b1 };
            if (mode == 0) {
                int h = n >> 6, d = n & 63;
                int bb0 = mA >> 11, s0 = mA & 2047;
                *(float2*)(out + (((size_t)(bb0 * HEADS + h) * SEQ + s0) * DK + d)) = v0;
                int m2 = mA + 8;
                int bb1 = m2 >> 11, s1 = m2 & 2047;
                *(float2*)(out + (((size_t)(bb1 * HEADS + h) * SEQ + s1) * DK + d)) = v1;
            } else {
                *(float2*)(out + (size_t)mA * DMODEL + n) = v0;
                *(float2*)(out + (size_t)(mA + 8) * DMODEL + n) = v1;
            }
        }
    }
}

// ---------------- Flash attention (fp32 SIMT, same as R2 pass) ---------------
#define QK_STRIDE 65

__global__ __launch_bounds__(256) void attn_kernel(
    const float* __restrict__ Q, const float* __restrict__ K,
    const float* __restrict__ V, float* __restrict__ out)
{
    extern __shared__ float sm[];
    float* QsT = sm;
    float* KsT = sm + 64 * QK_STRIDE;
    float* Vs  = sm + 2 * 64 * QK_STRIDE;
    float* Ps  = sm + 2 * 64 * QK_STRIDE + 64 * 64;

    const int tid = threadIdx.x;
    const int tx = tid & 15;
    const int ty = tid >> 4;
    const int qt = blockIdx.x;
    const int bh = blockIdx.y;
    const int bb = bh >> 4;
    const int hh = bh & 15;

    const float* Qp = Q + ((size_t)bh * SEQ + qt * 64) * DK;
    const float* Kp = K + (size_t)bh * SEQ * DK;
    const float* Vp = V + (size_t)bh * SEQ * DK;

    {
        const float sc = 0.125f;
        #pragma unroll
        for (int it = 0; it < 4; it++) {
            int idx = tid + it * 256;
            int row = idx >> 4, cg = idx & 15;
            float4 v = *(const float4*)(Qp + (size_t)row * DK + cg * 4);
            QsT[(cg * 4 + 0) * QK_STRIDE + row] = v.x * sc;
            QsT[(cg * 4 + 1) * QK_STRIDE + row] = v.y * sc;
            QsT[(cg * 4 + 2) * QK_STRIDE + row] = v.z * sc;
            QsT[(cg * 4 + 3) * QK_STRIDE + row] = v.w * sc;
        }
    }

    float m_i[4], l_i[4], O[4][4];
    #pragma unroll
    for (int i = 0; i < 4; i++) {
        m_i[i] = -1e30f; l_i[i] = 0.f;
        #pragma unroll
        for (int j = 0; j < 4; j++) O[i][j] = 0.f;
    }

    for (int kt = 0; kt < SEQ / 64; kt++) {
        __syncthreads();
        #pragma unroll
        for (int it = 0; it < 4; it++) {
            int idx = tid + it * 256;
            int row = idx >> 4, cg = idx & 15;
            float4 v = *(const float4*)(Kp + (size_t)(kt * 64 + row) * DK + cg * 4);
            KsT[(cg * 4 + 0) * QK_STRIDE + row] = v.x;
            KsT[(cg * 4 + 1) * QK_STRIDE + row] = v.y;
            KsT[(cg * 4 + 2) * QK_STRIDE + row] = v.z;
            KsT[(cg * 4 + 3) * QK_STRIDE + row] = v.w;
            float4 w = *(const float4*)(Vp + (size_t)(kt * 64 + row) * DK + cg * 4);
            *(float4*)&Vs[row * 64 + cg * 4] = w;
        }
        __syncthreads();

        float s[4][4] = {};
        #pragma unroll
        for (int kk = 0; kk < 64; kk++) {
            float a[4], b[4];
            #pragma unroll
            for (int i = 0; i < 4; i++) a[i] = QsT[kk * QK_STRIDE + ty * 4 + i];
            #pragma unroll
            for (int j = 0; j < 4; j++) b[j] = KsT[kk * QK_STRIDE + tx * 4 + j];
            #pragma unroll
            for (int i = 0; i < 4; i++)
                #pragma unroll
                for (int j = 0; j < 4; j++)
                    s[i][j] = fmaf(a[i], b[j], s[i][j]);
        }

        #pragma unroll
        for (int i = 0; i < 4; i++) {
            float rm = fmaxf(fmaxf(s[i][0], s[i][1]), fmaxf(s[i][2], s[i][3]));
            #pragma unroll
            for (int off = 8; off > 0; off >>= 1)
                rm = fmaxf(rm, __shfl_xor_sync(0xffffffffu, rm, off));
            float mn = fmaxf(m_i[i], rm);
            float corr = __expf(m_i[i] - mn);
            float rs = 0.f;
            #pragma unroll
            for (int j = 0; j < 4; j++) {
                float p = __expf(s[i][j] - mn);
                s[i][j] = p;
                rs += p;
            }
            #pragma unroll
            for (int off = 8; off > 0; off >>= 1)
                rs += __shfl_xor_sync(0xffffffffu, rs, off);
            l_i[i] = l_i[i] * corr + rs;
            m_i[i] = mn;
            #pragma unroll
            for (int j = 0; j < 4; j++) {
                O[i][j] *= corr;
                Ps[(ty * 4 + i) * 65 + tx * 4 + j] = s[i][j];
            }
        }
        __syncthreads();

        #pragma unroll
        for (int kk = 0; kk < 64; kk++) {
            float p[4], v[4];
            #pragma unroll
            for (int i = 0; i < 4; i++) p[i] = Ps[(ty * 4 + i) * 65 + kk];
            #pragma unroll
            for (int j = 0; j < 4; j++) v[j] = Vs[kk * 64 + tx * 4 + j];
            #pragma unroll
            for (int i = 0; i < 4; i++)
                #pragma unroll
                for (int j = 0; j < 4; j++)
                    O[i][j] = fmaf(p[i], v[j], O[i][j]);
        }
    }

    #pragma unroll
    for (int i = 0; i < 4; i++) {
        float inv_l = 1.0f / l_i[i];
        int srow = qt * 64 + ty * 4 + i;
        #pragma unroll
        for (int j = 0; j < 4; j++) {
            int d = tx * 4 + j;
            out[((size_t)bb * SEQ + srow) * DMODEL + hh * DK + d] = O[i][j] * inv_l;
        }
    }
}

// ---------------------------------------------------------------------------
// Launch
// ---------------------------------------------------------------------------
extern "C" void kernel_launch(void* const* d_in, const int* in_sizes, int n_in,
                              void* d_out, int out_size)
{
    const float* x  = (const float*)d_in[0];
    const float* wq = (const float*)d_in[1];
    const float* bq = (const float*)d_in[2];
    const float* wk = (const float*)d_in[3];
    const float* bk = (const float*)d_in[4];
    const float* wv = (const float*)d_in[5];
    const float* bv = (const float*)d_in[6];
    const float* wo = (const float*)d_in[7];
    const float* bo = (const float*)d_in[8];
    float* out = (float*)d_out;

    float *q_p, *k_p, *v_p, *ao_p;
    __nv_bfloat16 *xhi, *xlo, *aohi, *aolo, *wthi, *wtlo;
    cudaGetSymbolAddress((void**)&q_p,  g_q);
    cudaGetSymbolAddress((void**)&k_p,  g_k);
    cudaGetSymbolAddress((void**)&v_p,  g_v);
    cudaGetSymbolAddress((void**)&ao_p, g_ao);
    cudaGetSymbolAddress((void**)&xhi,  g_xhi);
    cudaGetSymbolAddress((void**)&xlo,  g_xlo);
    cudaGetSymbolAddress((void**)&aohi, g_aohi);
    cudaGetSymbolAddress((void**)&aolo, g_aolo);
    cudaGetSymbolAddress((void**)&wthi, g_wthi);
    cudaGetSymbolAddress((void**)&wtlo, g_wtlo);

    const int attn_smem = (2 * 64 * QK_STRIDE + 64 * 64 + 64 * 65) * (int)sizeof(float);
    cudaFuncSetAttribute(attn_kernel,
                         cudaFuncAttributeMaxDynamicSharedMemorySize, attn_smem);
    cudaFuncSetAttribute(gemm_mma,
                         cudaFuncAttributeMaxDynamicSharedMemorySize, GEMM_SMEM);

    // 1. split x
    int n4 = MROWS * DMODEL / 4;
    split_kernel<<<(n4 + 255) / 256, 256>>>(x, xhi, xlo, n4);

    // 2. transpose+split weights
    dim3 tgrid(DMODEL / 32, DMODEL / 32);
    wtrans_kernel<<<tgrid, 256>>>(wq, wthi + 0 * WSZ, wtlo + 0 * WSZ);
    wtrans_kernel<<<tgrid, 256>>>(wk, wthi + 1 * WSZ, wtlo + 1 * WSZ);
    wtrans_kernel<<<tgrid, 256>>>(wv, wthi + 2 * WSZ, wtlo + 2 * WSZ);
    wtrans_kernel<<<tgrid, 256>>>(wo, wthi + 3 * WSZ, wtlo + 3 * WSZ);

    // 3. QKV projections (tensor cores via mma.sync)
    dim3 ggrid(DMODEL / 128, MROWS / 128);   // (8, 64)
    gemm_mma<<<ggrid, 256, GEMM_SMEM>>>(xhi, xlo, wthi + 0 * WSZ, wtlo + 0 * WSZ, bq, q_p, 0);
    gemm_mma<<<ggrid, 256, GEMM_SMEM>>>(xhi, xlo, wthi + 1 * WSZ, wtlo + 1 * WSZ, bk, k_p, 0);
    gemm_mma<<<ggrid, 256, GEMM_SMEM>>>(xhi, xlo, wthi + 2 * WSZ, wtlo + 2 * WSZ, bv, v_p, 0);

    // 4. attention (fp32 SIMT)
    dim3 attn_grid(SEQ / 64, BATCH * HEADS);
    attn_kernel<<<attn_grid, 256, attn_smem>>>(q_p, k_p, v_p, ao_p);

    // 5. split attention output, final projection
    split_kernel<<<(n4 + 255) / 256, 256>>>(ao_p, aohi, aolo, n4);
    gemm_mma<<<ggrid, 256, GEMM_SMEM>>>(aohi, aolo, wthi + 3 * WSZ, wtlo + 3 * WSZ, bo, out, 1);
}

// round 5
// speedup vs baseline: 3.0605x; 2.0732x over previous
#include <cuda_runtime.h>
#include <cuda_bf16.h>
#include <cstdint>

// ---------------------------------------------------------------------------
// MultiHeadAttention: B=4, S=2048, D=1024, H=16, Dk=64, fp32.
// Round 5: HMMA everywhere. Projections and attention both mma.sync bf16
// with hi/lo 2-term split (fp32 accum). Splits fused into epilogues.
// ---------------------------------------------------------------------------

#define BATCH 4
#define SEQ   2048
#define DMODEL 1024
#define HEADS 16
#define DK    64
#define MROWS (BATCH * SEQ)          // 8192
#define WSZ   (DMODEL * DMODEL)

// ---------------- scratch ----------------------------------------------------
__device__ __align__(128) __nv_bfloat16 g_xhi[MROWS * DMODEL];
__device__ __align__(128) __nv_bfloat16 g_xlo[MROWS * DMODEL];
__device__ __align__(128) __nv_bfloat16 g_qhi[MROWS * DMODEL];
__device__ __align__(128) __nv_bfloat16 g_qlo[MROWS * DMODEL];
__device__ __align__(128) __nv_bfloat16 g_khi[MROWS * DMODEL];
__device__ __align__(128) __nv_bfloat16 g_klo[MROWS * DMODEL];
__device__ __align__(128) __nv_bfloat16 g_vhi[MROWS * DMODEL];
__device__ __align__(128) __nv_bfloat16 g_vlo[MROWS * DMODEL];
__device__ __align__(128) __nv_bfloat16 g_aohi[MROWS * DMODEL];
__device__ __align__(128) __nv_bfloat16 g_aolo[MROWS * DMODEL];
__device__ __align__(128) __nv_bfloat16 g_wthi[4 * WSZ];   // [N,K] transposed
__device__ __align__(128) __nv_bfloat16 g_wtlo[4 * WSZ];

// ---------------- PTX helpers ------------------------------------------------
__device__ __forceinline__ uint32_t smem_u32(const void* p) {
    uint32_t a;
    asm("{ .reg .u64 t; cvta.to.shared.u64 t, %1; cvt.u32.u64 %0, t; }"
        : "=r"(a) : "l"(p));
    return a;
}
__device__ __forceinline__ void ldsm_x4(uint32_t* r, uint32_t addr) {
    asm volatile("ldmatrix.sync.aligned.m8n8.x4.shared.b16 {%0,%1,%2,%3}, [%4];"
        : "=r"(r[0]), "=r"(r[1]), "=r"(r[2]), "=r"(r[3]) : "r"(addr));
}
__device__ __forceinline__ void ldsm_x4_t(uint32_t* r, uint32_t addr) {
    asm volatile("ldmatrix.sync.aligned.m8n8.x4.trans.shared.b16 {%0,%1,%2,%3}, [%4];"
        : "=r"(r[0]), "=r"(r[1]), "=r"(r[2]), "=r"(r[3]) : "r"(addr));
}
__device__ __forceinline__ void ldsm_x2(uint32_t* r, uint32_t addr) {
    asm volatile("ldmatrix.sync.aligned.m8n8.x2.shared.b16 {%0,%1}, [%2];"
        : "=r"(r[0]), "=r"(r[1]) : "r"(addr));
}
__device__ __forceinline__ void mma_bf16(float* c, const uint32_t* a, const uint32_t* b) {
    asm volatile(
        "mma.sync.aligned.m16n8k16.row.col.f32.bf16.bf16.f32 "
        "{%0,%1,%2,%3}, {%4,%5,%6,%7}, {%8,%9}, {%0,%1,%2,%3};"
        : "+f"(c[0]), "+f"(c[1]), "+f"(c[2]), "+f"(c[3])
        : "r"(a[0]), "r"(a[1]), "r"(a[2]), "r"(a[3]), "r"(b[0]), "r"(b[1]));
}
#define CP_ASYNC16(dst, src) \
    asm volatile("cp.async.cg.shared.global [%0], [%1], 16;" \
                 :: "r"(dst), "l"(src))
#define CP_COMMIT() asm volatile("cp.async.commit_group;" ::: "memory")
#define CP_WAIT(n)  asm volatile("cp.async.wait_group %0;" :: "n"(n) : "memory")

__device__ __forceinline__ uint32_t pack2bf(float a, float b) {
    __nv_bfloat162 t = __floats2bfloat162_rn(a, b);
    return *(uint32_t*)&t;
}

// ---------------- transpose+split: W[K,N] fp32 -> Wt[N,K] bf16 hi/lo ---------
__global__ __launch_bounds__(256) void wtrans_kernel(
    const float* __restrict__ W, __nv_bfloat16* __restrict__ Th,
    __nv_bfloat16* __restrict__ Tl)
{
    __shared__ float tile[32][33];
    const int n0 = blockIdx.x * 32, k0 = blockIdx.y * 32;
    const int tx = threadIdx.x & 31, ty = threadIdx.x >> 5;
    #pragma unroll
    for (int r = 0; r < 4; r++)
        tile[ty + 8 * r][tx] = W[(size_t)(k0 + ty + 8 * r) * DMODEL + n0 + tx];
    __syncthreads();
    #pragma unroll
    for (int r = 0; r < 4; r++) {
        int n = n0 + ty + 8 * r, k = k0 + tx;
        float v = tile[tx][ty + 8 * r];
        __nv_bfloat16 h = __float2bfloat16(v);
        __nv_bfloat16 l = __float2bfloat16(v - __bfloat162float(h));
        Th[(size_t)n * DMODEL + k] = h;
        Tl[(size_t)n * DMODEL + k] = l;
    }
}

// ---------------- split x: fp32 -> bf16 hi/lo ---------------------------------
__global__ __launch_bounds__(256) void split_kernel(
    const float* __restrict__ in, __nv_bfloat16* __restrict__ hi,
    __nv_bfloat16* __restrict__ lo, int n4)
{
    int i = blockIdx.x * 256 + threadIdx.x;
    if (i >= n4) return;
    float4 v = ((const float4*)in)[i];
    __nv_bfloat16 h[4], l[4];
    float f[4] = {v.x, v.y, v.z, v.w};
    #pragma unroll
    for (int j = 0; j < 4; j++) {
        h[j] = __float2bfloat16(f[j]);
        l[j] = __float2bfloat16(f[j] - __bfloat162float(h[j]));
    }
    ((uint2*)hi)[i] = *(uint2*)h;
    ((uint2*)lo)[i] = *(uint2*)l;
}

// ---------------- mma.sync GEMM ----------------------------------------------
// mode 0: emit bf16 hi/lo, scattered to [B,H,S,Dk] (i.e. [bh,s,d]), scaled.
// mode 1: emit fp32 row-major [M, N].
#define BK 64
#define NCHUNK (DMODEL / BK)
#define ROWB 144
#define TILE_BYTES (128 * ROWB)
#define STAGE_BYTES (4 * TILE_BYTES)
#define GEMM_SMEM (2 * STAGE_BYTES)

__global__ __launch_bounds__(256, 1) void gemm_mma(
    const __nv_bfloat16* __restrict__ Ah, const __nv_bfloat16* __restrict__ Al,
    const __nv_bfloat16* __restrict__ Bh, const __nv_bfloat16* __restrict__ Bl,
    const float* __restrict__ bias,
    __nv_bfloat16* __restrict__ ohi, __nv_bfloat16* __restrict__ olo,
    float* __restrict__ ofp, float scale, int mode)
{
    extern __shared__ char smem[];
    const uint32_t sbase = smem_u32(smem);
    const int tid = threadIdx.x;
    const int wid = tid >> 5, lane = tid & 31;
    const int n0 = blockIdx.x * 128;
    const int m0 = blockIdx.y * 128;

    const int warp_m = (wid & 1) * 64;
    const int warp_n = (wid >> 1) * 32;

    const __nv_bfloat16* gp[4] = {
        Ah + (size_t)m0 * DMODEL, Al + (size_t)m0 * DMODEL,
        Bh + (size_t)n0 * DMODEL, Bl + (size_t)n0 * DMODEL };

    auto load_stage = [&](int s, int c) {
        const int k0 = c * BK;
        const uint32_t stage = sbase + s * STAGE_BYTES;
        #pragma unroll
        for (int t = 0; t < 4; t++) {
            #pragma unroll
            for (int i = 0; i < 4; i++) {
                int idx = tid + i * 256;
                int row = idx >> 3;
                int ch  = idx & 7;
                uint32_t dst = stage + t * TILE_BYTES + row * ROWB + ch * 16;
                const __nv_bfloat16* src = gp[t] + (size_t)row * DMODEL + k0 + ch * 8;
                CP_ASYNC16(dst, src);
            }
        }
    };

    float acc[4][4][4];
    #pragma unroll
    for (int i = 0; i < 4; i++)
        #pragma unroll
        for (int j = 0; j < 4; j++)
            #pragma unroll
            for (int q = 0; q < 4; q++) acc[i][j][q] = 0.f;

    load_stage(0, 0); CP_COMMIT();
    load_stage(1, 1); CP_COMMIT();

    const int a_row = lane & 15;
    const int a_kb  = (lane & 16) ? 16 : 0;
    const int b_row = lane & 7;
    const int b_kb  = (lane & 8) ? 16 : 0;

    for (int c = 0; c < NCHUNK; c++) {
        if (c + 1 < NCHUNK) { CP_WAIT(1); } else { CP_WAIT(0); }
        __syncthreads();

        const uint32_t stage = sbase + (c & 1) * STAGE_BYTES;
        const uint32_t tAh = stage;
        const uint32_t tAl = stage + TILE_BYTES;
        const uint32_t tBh = stage + 2 * TILE_BYTES;
        const uint32_t tBl = stage + 3 * TILE_BYTES;

        #pragma unroll
        for (int ks = 0; ks < BK / 16; ks++) {
            uint32_t ah[4][4], al[4][4], bh[4][2], bl[4][2];
            #pragma unroll
            for (int mf = 0; mf < 4; mf++) {
                uint32_t off = (uint32_t)((warp_m + mf * 16 + a_row) * ROWB
                                          + ks * 32 + a_kb);
                ldsm_x4(ah[mf], tAh + off);
                ldsm_x4(al[mf], tAl + off);
            }
            #pragma unroll
            for (int nf = 0; nf < 4; nf++) {
                uint32_t off = (uint32_t)((warp_n + nf * 8 + b_row) * ROWB
                                          + ks * 32 + b_kb);
                ldsm_x2(bh[nf], tBh + off);
                ldsm_x2(bl[nf], tBl + off);
            }
            #pragma unroll
            for (int mf = 0; mf < 4; mf++)
                #pragma unroll
                for (int nf = 0; nf < 4; nf++) {
                    mma_bf16(acc[mf][nf], ah[mf], bh[nf]);
                    mma_bf16(acc[mf][nf], ah[mf], bl[nf]);
                    mma_bf16(acc[mf][nf], al[mf], bh[nf]);
                }
        }
        __syncthreads();
        if (c + 2 < NCHUNK) { load_stage(c & 1, c + 2); CP_COMMIT(); }
    }

    #pragma unroll
    for (int mf = 0; mf < 4; mf++) {
        const int mA = m0 + warp_m + mf * 16 + (lane >> 2);
        #pragma unroll
        for (int nf = 0; nf < 4; nf++) {
            const int n = n0 + warp_n + nf * 8 + (lane & 3) * 2;
            const float b0 = bias[n], b1 = bias[n + 1];
            float v0 = (acc[mf][nf][0] + b0) * scale;
            float v1 = (acc[mf][nf][1] + b1) * scale;
            float v2 = (acc[mf][nf][2] + b0) * scale;
            float v3 = (acc[mf][nf][3] + b1) * scale;
            if (mode == 0) {
                int h = n >> 6, d = n & 63;
                int bb0 = mA >> 11, s0 = mA & 2047;
                size_t i0 = ((size_t)(bb0 * HEADS + h) * SEQ + s0) * DK + d;
                int m2 = mA + 8;
                int bb1 = m2 >> 11, s1 = m2 & 2047;
                size_t i1 = ((size_t)(bb1 * HEADS + h) * SEQ + s1) * DK + d;
                __nv_bfloat16 h0 = __float2bfloat16(v0), h1 = __float2bfloat16(v1);
                __nv_bfloat16 h2 = __float2bfloat16(v2), h3 = __float2bfloat16(v3);
                *(uint32_t*)(ohi + i0) = pack2bf(v0, v1) ;
                *(uint32_t*)(olo + i0) = pack2bf(v0 - __bfloat162float(h0),
                                                 v1 - __bfloat162float(h1));
                *(uint32_t*)(ohi + i1) = pack2bf(v2, v3);
                *(uint32_t*)(olo + i1) = pack2bf(v2 - __bfloat162float(h2),
                                                 v3 - __bfloat162float(h3));
            } else {
                float2 w0 = {v0, v1}, w1 = {v2, v3};
                *(float2*)(ofp + (size_t)mA * DMODEL + n) = w0;
                *(float2*)(ofp + (size_t)(mA + 8) * DMODEL + n) = w1;
            }
        }
    }
}

// ---------------- HMMA flash attention ---------------------------------------
// CTA: 128 q rows x one (b,h). 8 warps x 16 q rows. KV tiles of 64, dbuf.
// QK: 3-term bf16 split. P re-split in regs. PV: 3-term. Out: bf16 hi/lo.
#define AT_RB 144
#define AT_QB (128 * AT_RB)     // 18432
#define AT_KB (64 * AT_RB)      // 9216
#define AT_OQH 0u
#define AT_OQL 18432u
#define AT_OK  36864u           // + buf*18432 + hl*9216
#define AT_OV  73728u
#define AT_SMEM 110592

__global__ __launch_bounds__(256, 1) void attn_mma(
    const __nv_bfloat16* __restrict__ Qh, const __nv_bfloat16* __restrict__ Ql,
    const __nv_bfloat16* __restrict__ Kh, const __nv_bfloat16* __restrict__ Kl,
    const __nv_bfloat16* __restrict__ Vh, const __nv_bfloat16* __restrict__ Vl,
    __nv_bfloat16* __restrict__ Ohi, __nv_bfloat16* __restrict__ Olo)
{
    extern __shared__ char smem[];
    const uint32_t sb = smem_u32(smem);
    const int tid = threadIdx.x, wid = tid >> 5, lane = tid & 31;
    const int qt = blockIdx.x, bh = blockIdx.y;
    const int q0 = qt * 128;
    const size_t base = (size_t)bh * SEQ * DK;

    auto ld_q = [&] {
        #pragma unroll
        for (int i = 0; i < 8; i++) {
            int idx = tid + i * 256;           // 0..2047
            int hl = idx >> 10;
            int r  = (idx >> 3) & 127;
            int ch = idx & 7;
            const __nv_bfloat16* src = (hl ? Ql : Qh) + base + (size_t)(q0 + r) * DK + ch * 8;
            CP_ASYNC16(sb + (hl ? AT_OQL : AT_OQH) + r * AT_RB + ch * 16, src);
        }
    };
    auto ld_kv = [&](int buf, int t) {
        #pragma unroll
        for (int i = 0; i < 8; i++) {
            int idx = tid + i * 256;           // 0..2047
            int ts = idx >> 9;                 // 0 kh, 1 kl, 2 vh, 3 vl
            int r  = (idx >> 3) & 63;
            int ch = idx & 7;
            const __nv_bfloat16* sp =
                (ts == 0 ? Kh : ts == 1 ? Kl : ts == 2 ? Vh : Vl)
                + base + (size_t)(t * 64 + r) * DK + ch * 8;
            uint32_t dst = sb + (ts < 2 ? AT_OK : AT_OV) + buf * 18432
                           + (ts & 1) * 9216 + r * AT_RB + ch * 16;
            CP_ASYNC16(dst, sp);
        }
    };

    ld_q(); ld_kv(0, 0); CP_COMMIT();
    ld_kv(1, 1); CP_COMMIT();

    const int a_r = lane & 15;
    const int a_c = (lane & 16) ? 16 : 0;
    const int bm = lane >> 3;
    const int b_r = (bm & 1) * 8 + (lane & 7);   // K non-trans row within kv16
    const int b_c = (bm >> 1) * 16;              // byte col offset (d8)
    const int v_r = lane & 15;                   // V trans: kv row within k-step
    const int v_c = (lane & 16) ? 16 : 0;

    CP_WAIT(1); __syncthreads();

    const int wq = wid * 16;
    uint32_t qfh[4][4], qfl[4][4];
    #pragma unroll
    for (int t = 0; t < 4; t++) {
        ldsm_x4(qfh[t], sb + AT_OQH + (wq + a_r) * AT_RB + t * 32 + a_c);
        ldsm_x4(qfl[t], sb + AT_OQL + (wq + a_r) * AT_RB + t * 32 + a_c);
    }

    float of[8][4];
    #pragma unroll
    for (int j = 0; j < 8; j++)
        #pragma unroll
        for (int q = 0; q < 4; q++) of[j][q] = 0.f;
    float mrow0 = -1e30f, mrow1 = -1e30f, lrow0 = 0.f, lrow1 = 0.f;

    for (int c = 0; c < 32; c++) {
        if (c > 0) {
            if (c < 31) { CP_WAIT(1); } else { CP_WAIT(0); }
            __syncthreads();
        }
        const uint32_t kbuf = sb + AT_OK + (c & 1) * 18432;
        const uint32_t vbuf = sb + AT_OV + (c & 1) * 18432;

        // ---- S = Q K^T ----
        float sf[8][4];
        #pragma unroll
        for (int j = 0; j < 8; j++)
            #pragma unroll
            for (int q = 0; q < 4; q++) sf[j][q] = 0.f;

        #pragma unroll
        for (int t = 0; t < 4; t++) {
            uint32_t kfh[8][2], kfl[8][2];
            #pragma unroll
            for (int g = 0; g < 4; g++) {
                uint32_t r4[4];
                uint32_t ad = kbuf + (g * 16 + b_r) * AT_RB + t * 32 + b_c;
                ldsm_x4(r4, ad);
                kfh[2*g][0] = r4[0]; kfh[2*g][1] = r4[2];
                kfh[2*g+1][0] = r4[1]; kfh[2*g+1][1] = r4[3];
                ldsm_x4(r4, ad + 9216);
                kfl[2*g][0] = r4[0]; kfl[2*g][1] = r4[2];
                kfl[2*g+1][0] = r4[1]; kfl[2*g+1][1] = r4[3];
            }
            #pragma unroll
            for (int j = 0; j < 8; j++) {
                mma_bf16(sf[j], qfh[t], kfh[j]);
                mma_bf16(sf[j], qfh[t], kfl[j]);
                mma_bf16(sf[j], qfl[t], kfh[j]);
            }
        }

        // ---- online softmax ----
        float tm0 = -1e30f, tm1 = -1e30f;
        #pragma unroll
        for (int j = 0; j < 8; j++) {
            tm0 = fmaxf(tm0, fmaxf(sf[j][0], sf[j][1]));
            tm1 = fmaxf(tm1, fmaxf(sf[j][2], sf[j][3]));
        }
        tm0 = fmaxf(tm0, __shfl_xor_sync(0xffffffffu, tm0, 1));
        tm0 = fmaxf(tm0, __shfl_xor_sync(0xffffffffu, tm0, 2));
        tm1 = fmaxf(tm1, __shfl_xor_sync(0xffffffffu, tm1, 1));
        tm1 = fmaxf(tm1, __shfl_xor_sync(0xffffffffu, tm1, 2));
        float mn0 = fmaxf(mrow0, tm0), mn1 = fmaxf(mrow1, tm1);
        float cor0 = __expf(mrow0 - mn0), cor1 = __expf(mrow1 - mn1);
        float rs0 = 0.f, rs1 = 0.f;
        #pragma unroll
        for (int j = 0; j < 8; j++) {
            sf[j][0] = __expf(sf[j][0] - mn0);
            sf[j][1] = __expf(sf[j][1] - mn0);
            sf[j][2] = __expf(sf[j][2] - mn1);
            sf[j][3] = __expf(sf[j][3] - mn1);
            rs0 += sf[j][0] + sf[j][1];
            rs1 += sf[j][2] + sf[j][3];
        }
        rs0 += __shfl_xor_sync(0xffffffffu, rs0, 1);
        rs0 += __shfl_xor_sync(0xffffffffu, rs0, 2);
        rs1 += __shfl_xor_sync(0xffffffffu, rs1, 1);
        rs1 += __shfl_xor_sync(0xffffffffu, rs1, 2);
        lrow0 = lrow0 * cor0 + rs0;
        lrow1 = lrow1 * cor1 + rs1;
        mrow0 = mn0; mrow1 = mn1;
        #pragma unroll
        for (int j = 0; j < 8; j++) {
            of[j][0] *= cor0; of[j][1] *= cor0;
            of[j][2] *= cor1; of[j][3] *= cor1;
        }

        // ---- P -> bf16 hi/lo A-fragments ----
        uint32_t ph[4][4], pl[4][4];
        #pragma unroll
        for (int t = 0; t < 4; t++) {
            #pragma unroll
            for (int half = 0; half < 2; half++) {
                const float* p2 = sf[2 * t + half];
                __nv_bfloat16 h0 = __float2bfloat16(p2[0]);
                __nv_bfloat16 h1 = __float2bfloat16(p2[1]);
                __nv_bfloat16 h2 = __float2bfloat16(p2[2]);
                __nv_bfloat16 h3 = __float2bfloat16(p2[3]);
                ph[t][2 * half + 0] = pack2bf(p2[0], p2[1]);
                ph[t][2 * half + 1] = pack2bf(p2[2], p2[3]);
                pl[t][2 * half + 0] = pack2bf(p2[0] - __bfloat162float(h0),
                                              p2[1] - __bfloat162float(h1));
                pl[t][2 * half + 1] = pack2bf(p2[2] - __bfloat162float(h2),
                                              p2[3] - __bfloat162float(h3));
            }
        }

        // ---- O += P V ----
        #pragma unroll
        for (int t = 0; t < 4; t++) {
            uint32_t vfh[8][2], vfl[8][2];
            #pragma unroll
            for (int g = 0; g < 4; g++) {
                uint32_t r4[4];
                uint32_t ad = vbuf + (t * 16 + v_r) * AT_RB + g * 32 + v_c;
                ldsm_x4_t(r4, ad);
                vfh[2*g][0] = r4[0]; vfh[2*g][1] = r4[1];
                vfh[2*g+1][0] = r4[2]; vfh[2*g+1][1] = r4[3];
                ldsm_x4_t(r4, ad + 9216);
                vfl[2*g][0] = r4[0]; vfl[2*g][1] = r4[1];
                vfl[2*g+1][0] = r4[2]; vfl[2*g+1][1] = r4[3];
            }
            #pragma unroll
            for (int j = 0; j < 8; j++) {
                mma_bf16(of[j], ph[t], vfh[j]);
                mma_bf16(of[j], ph[t], vfl[j]);
                mma_bf16(of[j], pl[t], vfh[j]);
            }
        }

        __syncthreads();
        if (c + 2 < 32) { ld_kv(c & 1, c + 2); CP_COMMIT(); }
    }

    // ---- epilogue: O/l -> bf16 hi/lo, [B, S, H*Dk] ----
    const float inv0 = 1.f / lrow0, inv1 = 1.f / lrow1;
    const int r0 = q0 + wq + (lane >> 2), r1 = r0 + 8;
    const int b_ = bh >> 4, h_ = bh & 15;
    #pragma unroll
    for (int j = 0; j < 8; j++) {
        int d = j * 8 + (lane & 3) * 2;
        float a0 = of[j][0] * inv0, a1 = of[j][1] * inv0;
        float a2 = of[j][2] * inv1, a3 = of[j][3] * inv1;
        size_t i0 = ((size_t)b_ * SEQ + r0) * DMODEL + h_ * 64 + d;
        size_t i1 = ((size_t)b_ * SEQ + r1) * DMODEL + h_ * 64 + d;
        __nv_bfloat16 h0 = __float2bfloat16(a0), h1 = __float2bfloat16(a1);
        __nv_bfloat16 h2 = __float2bfloat16(a2), h3 = __float2bfloat16(a3);
        *(uint32_t*)(Ohi + i0) = pack2bf(a0, a1);
        *(uint32_t*)(Olo + i0) = pack2bf(a0 - __bfloat162float(h0),
                                         a1 - __bfloat162float(h1));
        *(uint32_t*)(Ohi + i1) = pack2bf(a2, a3);
        *(uint32_t*)(Olo + i1) = pack2bf(a2 - __bfloat162float(h2),
                                         a3 - __bfloat162float(h3));
    }
}

// ---------------------------------------------------------------------------
// Launch
// ---------------------------------------------------------------------------
extern "C" void kernel_launch(void* const* d_in, const int* in_sizes, int n_in,
                              void* d_out, int out_size)
{
    const float* x  = (const float*)d_in[0];
    const float* wq = (const float*)d_in[1];
    const float* bq = (const float*)d_in[2];
    const float* wk = (const float*)d_in[3];
    const float* bk = (const float*)d_in[4];
    const float* wv = (const float*)d_in[5];
    const float* bv = (const float*)d_in[6];
    const float* wo = (const float*)d_in[7];
    const float* bo = (const float*)d_in[8];
    float* out = (float*)d_out;

    __nv_bfloat16 *xhi, *xlo, *qhi, *qlo, *khi, *klo, *vhi, *vlo;
    __nv_bfloat16 *aohi, *aolo, *wthi, *wtlo;
    cudaGetSymbolAddress((void**)&xhi,  g_xhi);
    cudaGetSymbolAddress((void**)&xlo,  g_xlo);
    cudaGetSymbolAddress((void**)&qhi,  g_qhi);
    cudaGetSymbolAddress((void**)&qlo,  g_qlo);
    cudaGetSymbolAddress((void**)&khi,  g_khi);
    cudaGetSymbolAddress((void**)&klo,  g_klo);
    cudaGetSymbolAddress((void**)&vhi,  g_vhi);
    cudaGetSymbolAddress((void**)&vlo,  g_vlo);
    cudaGetSymbolAddress((void**)&aohi, g_aohi);
    cudaGetSymbolAddress((void**)&aolo, g_aolo);
    cudaGetSymbolAddress((void**)&wthi, g_wthi);
    cudaGetSymbolAddress((void**)&wtlo, g_wtlo);

    cudaFuncSetAttribute(gemm_mma,
                         cudaFuncAttributeMaxDynamicSharedMemorySize, GEMM_SMEM);
    cudaFuncSetAttribute(attn_mma,
                         cudaFuncAttributeMaxDynamicSharedMemorySize, AT_SMEM);

    // 1. split x
    int n4 = MROWS * DMODEL / 4;
    split_kernel<<<(n4 + 255) / 256, 256>>>(x, xhi, xlo, n4);

    // 2. transpose+split weights
    dim3 tgrid(DMODEL / 32, DMODEL / 32);
    wtrans_kernel<<<tgrid, 256>>>(wq, wthi + 0 * WSZ, wtlo + 0 * WSZ);
    wtrans_kernel<<<tgrid, 256>>>(wk, wthi + 1 * WSZ, wtlo + 1 * WSZ);
    wtrans_kernel<<<tgrid, 256>>>(wv, wthi + 2 * WSZ, wtlo + 2 * WSZ);
    wtrans_kernel<<<tgrid, 256>>>(wo, wthi + 3 * WSZ, wtlo + 3 * WSZ);

    // 3. QKV projections -> bf16 hi/lo scattered [bh, s, d]; Q pre-scaled 1/8
    dim3 ggrid(DMODEL / 128, MROWS / 128);
    gemm_mma<<<ggrid, 256, GEMM_SMEM>>>(xhi, xlo, wthi + 0 * WSZ, wtlo + 0 * WSZ,
                                        bq, qhi, qlo, nullptr, 0.125f, 0);
    gemm_mma<<<ggrid, 256, GEMM_SMEM>>>(xhi, xlo, wthi + 1 * WSZ, wtlo + 1 * WSZ,
                                        bk, khi, klo, nullptr, 1.0f, 0);
    gemm_mma<<<ggrid, 256, GEMM_SMEM>>>(xhi, xlo, wthi + 2 * WSZ, wtlo + 2 * WSZ,
                                        bv, vhi, vlo, nullptr, 1.0f, 0);

    // 4. attention (HMMA) -> aohi/aolo [B, S, 1024]
    dim3 agrid(SEQ / 128, BATCH * HEADS);   // (16, 64)
    attn_mma<<<agrid, 256, AT_SMEM>>>(qhi, qlo, khi, klo, vhi, vlo, aohi, aolo);

    // 5. final projection -> fp32 out
    gemm_mma<<<ggrid, 256, GEMM_SMEM>>>(aohi, aolo, wthi + 3 * WSZ, wtlo + 3 * WSZ,
                                        bo, nullptr, nullptr, out, 1.0f, 1);
}

// round 6
// speedup vs baseline: 3.0831x; 1.0074x over previous
#include <cuda_runtime.h>
#include <cuda_bf16.h>
#include <cstdint>

// ---------------------------------------------------------------------------
// MultiHeadAttention: B=4, S=2048, D=1024, H=16, Dk=64, fp32.
// Round 6: fused QKV GEMM (N=3072), 64x64 warp tiles, BK=32, 3-stage
// single-sync cp.async pipeline. Attention pipeline upgraded likewise.
// ---------------------------------------------------------------------------

#define BATCH 4
#define SEQ   2048
#define DMODEL 1024
#define HEADS 16
#define DK    64
#define MROWS (BATCH * SEQ)          // 8192
#define WSZ   (DMODEL * DMODEL)
#define PSZ   (MROWS * DMODEL)       // 8M elements per projection

// ---------------- scratch ----------------------------------------------------
__device__ __align__(128) __nv_bfloat16 g_xhi[PSZ];
__device__ __align__(128) __nv_bfloat16 g_xlo[PSZ];
__device__ __align__(128) __nv_bfloat16 g_qkvhi[3 * PSZ];  // q,k,v [bh,s,d]
__device__ __align__(128) __nv_bfloat16 g_qkvlo[3 * PSZ];
__device__ __align__(128) __nv_bfloat16 g_aohi[PSZ];
__device__ __align__(128) __nv_bfloat16 g_aolo[PSZ];
__device__ __align__(128) __nv_bfloat16 g_wthi[4 * WSZ];   // [N,K]: q,k,v,o
__device__ __align__(128) __nv_bfloat16 g_wtlo[4 * WSZ];
__device__ __align__(128) float g_bias[3 * DMODEL];

// ---------------- PTX helpers ------------------------------------------------
__device__ __forceinline__ uint32_t smem_u32(const void* p) {
    uint32_t a;
    asm("{ .reg .u64 t; cvta.to.shared.u64 t, %1; cvt.u32.u64 %0, t; }"
        : "=r"(a) : "l"(p));
    return a;
}
__device__ __forceinline__ void ldsm_x4(uint32_t* r, uint32_t addr) {
    asm volatile("ldmatrix.sync.aligned.m8n8.x4.shared.b16 {%0,%1,%2,%3}, [%4];"
        : "=r"(r[0]), "=r"(r[1]), "=r"(r[2]), "=r"(r[3]) : "r"(addr));
}
__device__ __forceinline__ void ldsm_x4_t(uint32_t* r, uint32_t addr) {
    asm volatile("ldmatrix.sync.aligned.m8n8.x4.trans.shared.b16 {%0,%1,%2,%3}, [%4];"
        : "=r"(r[0]), "=r"(r[1]), "=r"(r[2]), "=r"(r[3]) : "r"(addr));
}
__device__ __forceinline__ void mma_bf16(float* c, const uint32_t* a, const uint32_t* b) {
    asm volatile(
        "mma.sync.aligned.m16n8k16.row.col.f32.bf16.bf16.f32 "
        "{%0,%1,%2,%3}, {%4,%5,%6,%7}, {%8,%9}, {%0,%1,%2,%3};"
        : "+f"(c[0]), "+f"(c[1]), "+f"(c[2]), "+f"(c[3])
        : "r"(a[0]), "r"(a[1]), "r"(a[2]), "r"(a[3]), "r"(b[0]), "r"(b[1]));
}
#define CP_ASYNC16(dst, src) \
    asm volatile("cp.async.cg.shared.global [%0], [%1], 16;" \
                 :: "r"(dst), "l"(src))
#define CP_COMMIT() asm volatile("cp.async.commit_group;" ::: "memory")
#define CP_WAIT(n)  asm volatile("cp.async.wait_group %0;" :: "n"(n) : "memory")

__device__ __forceinline__ uint32_t pack2bf(float a, float b) {
    __nv_bfloat162 t = __floats2bfloat162_rn(a, b);
    return *(uint32_t*)&t;
}

// ---------------- prep kernels -------------------------------------------------
__global__ __launch_bounds__(256) void split_kernel(
    const float* __restrict__ in, __nv_bfloat16* __restrict__ hi,
    __nv_bfloat16* __restrict__ lo, int n4)
{
    int i = blockIdx.x * 256 + threadIdx.x;
    if (i >= n4) return;
    float4 v = ((const float4*)in)[i];
    __nv_bfloat16 h[4], l[4];
    float f[4] = {v.x, v.y, v.z, v.w};
    #pragma unroll
    for (int j = 0; j < 4; j++) {
        h[j] = __float2bfloat16(f[j]);
        l[j] = __float2bfloat16(f[j] - __bfloat162float(h[j]));
    }
    ((uint2*)hi)[i] = *(uint2*)h;
    ((uint2*)lo)[i] = *(uint2*)l;
}

__global__ __launch_bounds__(256) void wtrans_kernel(
    const float* __restrict__ W, __nv_bfloat16* __restrict__ Th,
    __nv_bfloat16* __restrict__ Tl)
{
    __shared__ float tile[32][33];
    const int n0 = blockIdx.x * 32, k0 = blockIdx.y * 32;
    const int tx = threadIdx.x & 31, ty = threadIdx.x >> 5;
    #pragma unroll
    for (int r = 0; r < 4; r++)
        tile[ty + 8 * r][tx] = W[(size_t)(k0 + ty + 8 * r) * DMODEL + n0 + tx];
    __syncthreads();
    #pragma unroll
    for (int r = 0; r < 4; r++) {
        int n = n0 + ty + 8 * r, k = k0 + tx;
        float v = tile[tx][ty + 8 * r];
        __nv_bfloat16 h = __float2bfloat16(v);
        __nv_bfloat16 l = __float2bfloat16(v - __bfloat162float(h));
        Th[(size_t)n * DMODEL + k] = h;
        Tl[(size_t)n * DMODEL + k] = l;
    }
}

__global__ void bias_concat(const float* bq, const float* bk, const float* bv,
                            float* dst)
{
    int i = blockIdx.x * 256 + threadIdx.x;
    if (i < DMODEL) {
        dst[i] = bq[i];
        dst[DMODEL + i] = bk[i];
        dst[2 * DMODEL + i] = bv[i];
    }
}

// ---------------- mma.sync GEMM (128m x 256n CTA, 64x64 warp, BK=32) ----------
// mode 0: fused QKV. N=3072. Emit bf16 hi/lo scattered to g_qkv*[proj][bh,s,d],
//         q part scaled by 1/8. bias = g_bias (3072).
// mode 1: final projection. N=1024. Emit fp32 row-major to ofp.
#define BK2 32
#define ROW2 80                        // 32 bf16 = 64B + 16B pad
#define A_TILE2 (128 * ROW2)           // 10240
#define B_TILE2 (256 * ROW2)           // 20480
#define STAGE2 (2 * A_TILE2 + 2 * B_TILE2)   // 61440
#define GEMM2_SMEM (3 * STAGE2)        // 184320
#define NCH2 (DMODEL / BK2)            // 32

__global__ __launch_bounds__(256, 1) void gemm_mma2(
    const __nv_bfloat16* __restrict__ Ah, const __nv_bfloat16* __restrict__ Al,
    const __nv_bfloat16* __restrict__ Bh, const __nv_bfloat16* __restrict__ Bl,
    const float* __restrict__ bias,
    __nv_bfloat16* __restrict__ ohi, __nv_bfloat16* __restrict__ olo,
    float* __restrict__ ofp, int mode)
{
    extern __shared__ char smem[];
    const uint32_t sbase = smem_u32(smem);
    const int tid = threadIdx.x;
    const int wid = tid >> 5, lane = tid & 31;
    const int n0 = blockIdx.x * 256;
    const int m0 = blockIdx.y * 128;

    const int warp_m = (wid & 1) * 64;
    const int warp_n = (wid >> 1) * 64;

    const __nv_bfloat16* gA[2] = { Ah + (size_t)m0 * DMODEL, Al + (size_t)m0 * DMODEL };
    const __nv_bfloat16* gB[2] = { Bh + (size_t)n0 * DMODEL, Bl + (size_t)n0 * DMODEL };

    auto load_stage = [&](int st, int c) {
        const int k0 = c * BK2;
        const uint32_t stage = sbase + st * STAGE2;
        // A: 2 tiles x 128 rows x 4 chunks = 1024 -> 4/thread
        #pragma unroll
        for (int i = 0; i < 4; i++) {
            int idx = tid + i * 256;
            int t = idx >> 9, row = (idx >> 2) & 127, ch = idx & 3;
            CP_ASYNC16(stage + t * A_TILE2 + row * ROW2 + ch * 16,
                       gA[t] + (size_t)row * DMODEL + k0 + ch * 8);
        }
        // B: 2 tiles x 256 rows x 4 chunks = 2048 -> 8/thread
        #pragma unroll
        for (int i = 0; i < 8; i++) {
            int idx = tid + i * 256;
            int t = idx >> 10, row = (idx >> 2) & 255, ch = idx & 3;
            CP_ASYNC16(stage + 2 * A_TILE2 + t * B_TILE2 + row * ROW2 + ch * 16,
                       gB[t] + (size_t)row * DMODEL + k0 + ch * 8);
        }
    };

    float acc[4][8][4];
    #pragma unroll
    for (int i = 0; i < 4; i++)
        #pragma unroll
        for (int j = 0; j < 8; j++)
            #pragma unroll
            for (int q = 0; q < 4; q++) acc[i][j][q] = 0.f;

    load_stage(0, 0); CP_COMMIT();
    load_stage(1, 1); CP_COMMIT();

    const int a_r = lane & 15;
    const int a_c = (lane & 16) ? 16 : 0;
    const int b_r = ((lane & 16) ? 8 : 0) + (lane & 7);
    const int b_c = (lane & 8) ? 16 : 0;

    for (int c = 0; c < NCH2; c++) {
        if (c + 2 < NCH2) { CP_WAIT(1); } else { CP_WAIT(0); }
        __syncthreads();
        if (c + 2 < NCH2) { load_stage((c + 2) % 3, c + 2); CP_COMMIT(); }

        const uint32_t stage = sbase + (c % 3) * STAGE2;
        const uint32_t tAh = stage;
        const uint32_t tAl = stage + A_TILE2;
        const uint32_t tBh = stage + 2 * A_TILE2;
        const uint32_t tBl = stage + 2 * A_TILE2 + B_TILE2;

        #pragma unroll
        for (int ks = 0; ks < 2; ks++) {
            uint32_t ah[4][4], al[4][4];
            #pragma unroll
            for (int mf = 0; mf < 4; mf++) {
                uint32_t off = (uint32_t)((warp_m + mf * 16 + a_r) * ROW2
                                          + ks * 32 + a_c);
                ldsm_x4(ah[mf], tAh + off);
                ldsm_x4(al[mf], tAl + off);
            }
            #pragma unroll
            for (int nfp = 0; nfp < 4; nfp++) {
                uint32_t off = (uint32_t)((warp_n + nfp * 16 + b_r) * ROW2
                                          + ks * 32 + b_c);
                uint32_t bh[4], bl[4];
                ldsm_x4(bh, tBh + off);
                ldsm_x4(bl, tBl + off);
                #pragma unroll
                for (int mf = 0; mf < 4; mf++) {
                    #pragma unroll
                    for (int j = 0; j < 2; j++) {
                        float* a_ = acc[mf][nfp * 2 + j];
                        mma_bf16(a_, ah[mf], bh + 2 * j);
                        mma_bf16(a_, ah[mf], bl + 2 * j);
                        mma_bf16(a_, al[mf], bh + 2 * j);
                    }
                }
            }
        }
    }

    // ---- epilogue ----
    #pragma unroll
    for (int mf = 0; mf < 4; mf++) {
        const int mA = m0 + warp_m + mf * 16 + (lane >> 2);
        #pragma unroll
        for (int nf = 0; nf < 8; nf++) {
            const int n = n0 + warp_n + nf * 8 + (lane & 3) * 2;
            const float b0 = bias[n], b1 = bias[n + 1];
            float v0 = acc[mf][nf][0] + b0;
            float v1 = acc[mf][nf][1] + b1;
            float v2 = acc[mf][nf][2] + b0;
            float v3 = acc[mf][nf][3] + b1;
            if (mode == 0) {
                const float sc = (n < DMODEL) ? 0.125f : 1.0f;
                v0 *= sc; v1 *= sc; v2 *= sc; v3 *= sc;
                int proj = n >> 10;
                int np = n & 1023;
                int h = np >> 6, d = np & 63;
                int bb0 = mA >> 11, s0 = mA & 2047;
                size_t i0 = (size_t)proj * PSZ
                          + ((size_t)(bb0 * HEADS + h) * SEQ + s0) * DK + d;
                int m2 = mA + 8;
                int bb1 = m2 >> 11, s1 = m2 & 2047;
                size_t i1 = (size_t)proj * PSZ
                          + ((size_t)(bb1 * HEADS + h) * SEQ + s1) * DK + d;
                __nv_bfloat16 h0 = __float2bfloat16(v0), h1 = __float2bfloat16(v1);
                __nv_bfloat16 h2 = __float2bfloat16(v2), h3 = __float2bfloat16(v3);
                *(uint32_t*)(ohi + i0) = pack2bf(v0, v1);
                *(uint32_t*)(olo + i0) = pack2bf(v0 - __bfloat162float(h0),
                                                 v1 - __bfloat162float(h1));
                *(uint32_t*)(ohi + i1) = pack2bf(v2, v3);
                *(uint32_t*)(olo + i1) = pack2bf(v2 - __bfloat162float(h2),
                                                 v3 - __bfloat162float(h3));
            } else {
                float2 w0 = {v0, v1}, w1 = {v2, v3};
                *(float2*)(ofp + (size_t)mA * DMODEL + n) = w0;
                *(float2*)(ofp + (size_t)(mA + 8) * DMODEL + n) = w1;
            }
        }
    }
}

// ---------------- HMMA flash attention (3-stage single-sync pipeline) ---------
#define AT_RB 144
#define AT_QH 0u
#define AT_QL 18432u
#define AT_STG 36864u           // + st*36864: Kh, Kl(+9216), Vh(+18432), Vl(+27648)
#define AT_SMEM (36864 + 3 * 36864)   // 147456

__global__ __launch_bounds__(256, 1) void attn_mma(
    const __nv_bfloat16* __restrict__ Qh, const __nv_bfloat16* __restrict__ Ql,
    const __nv_bfloat16* __restrict__ Kh, const __nv_bfloat16* __restrict__ Kl,
    const __nv_bfloat16* __restrict__ Vh, const __nv_bfloat16* __restrict__ Vl,
    __nv_bfloat16* __restrict__ Ohi, __nv_bfloat16* __restrict__ Olo)
{
    extern __shared__ char smem[];
    const uint32_t sb = smem_u32(smem);
    const int tid = threadIdx.x, wid = tid >> 5, lane = tid & 31;
    const int qt = blockIdx.x, bh = blockIdx.y;
    const int q0 = qt * 128;
    const size_t base = (size_t)bh * SEQ * DK;

    auto ld_q = [&] {
        #pragma unroll
        for (int i = 0; i < 8; i++) {
            int idx = tid + i * 256;
            int hl = idx >> 10;
            int r  = (idx >> 3) & 127;
            int ch = idx & 7;
            const __nv_bfloat16* src = (hl ? Ql : Qh) + base + (size_t)(q0 + r) * DK + ch * 8;
            CP_ASYNC16(sb + (hl ? AT_QL : AT_QH) + r * AT_RB + ch * 16, src);
        }
    };
    auto ld_kv = [&](int st, int t) {
        #pragma unroll
        for (int i = 0; i < 8; i++) {
            int idx = tid + i * 256;
            int ts = idx >> 9;                 // 0 kh, 1 kl, 2 vh, 3 vl
            int r  = (idx >> 3) & 63;
            int ch = idx & 7;
            const __nv_bfloat16* sp =
                (ts == 0 ? Kh : ts == 1 ? Kl : ts == 2 ? Vh : Vl)
                + base + (size_t)(t * 64 + r) * DK + ch * 8;
            CP_ASYNC16(sb + AT_STG + st * 36864 + ts * 9216 + r * AT_RB + ch * 16, sp);
        }
    };

    ld_q(); ld_kv(0, 0); CP_COMMIT();
    ld_kv(1, 1); CP_COMMIT();

    const int a_r = lane & 15;
    const int a_c = (lane & 16) ? 16 : 0;
    const int bm = lane >> 3;
    const int b_r = (bm & 1) * 8 + (lane & 7);
    const int b_c = (bm >> 1) * 16;
    const int v_r = lane & 15;
    const int v_c = (lane & 16) ? 16 : 0;

    const int wq = wid * 16;
    uint32_t qfh[4][4], qfl[4][4];

    float of[8][4];
    #pragma unroll
    for (int j = 0; j < 8; j++)
        #pragma unroll
        for (int q = 0; q < 4; q++) of[j][q] = 0.f;
    float mrow0 = -1e30f, mrow1 = -1e30f, lrow0 = 0.f, lrow1 = 0.f;

    for (int c = 0; c < 32; c++) {
        if (c + 2 < 32) { CP_WAIT(1); } else { CP_WAIT(0); }
        __syncthreads();
        if (c == 0) {
            #pragma unroll
            for (int t = 0; t < 4; t++) {
                ldsm_x4(qfh[t], sb + AT_QH + (wq + a_r) * AT_RB + t * 32 + a_c);
                ldsm_x4(qfl[t], sb + AT_QL + (wq + a_r) * AT_RB + t * 32 + a_c);
            }
        }
        if (c + 2 < 32) { ld_kv((c + 2) % 3, c + 2); CP_COMMIT(); }

        const uint32_t kbuf = sb + AT_STG + (c % 3) * 36864;
        const uint32_t vbuf = kbuf + 18432;

        // ---- S = Q K^T ----
        float sf[8][4];
        #pragma unroll
        for (int j = 0; j < 8; j++)
            #pragma unroll
            for (int q = 0; q < 4; q++) sf[j][q] = 0.f;

        #pragma unroll
        for (int t = 0; t < 4; t++) {
            uint32_t kfh[8][2], kfl[8][2];
            #pragma unroll
            for (int g = 0; g < 4; g++) {
                uint32_t r4[4];
                uint32_t ad = kbuf + (g * 16 + b_r) * AT_RB + t * 32 + b_c;
                ldsm_x4(r4, ad);
                kfh[2*g][0] = r4[0]; kfh[2*g][1] = r4[2];
                kfh[2*g+1][0] = r4[1]; kfh[2*g+1][1] = r4[3];
                ldsm_x4(r4, ad + 9216);
                kfl[2*g][0] = r4[0]; kfl[2*g][1] = r4[2];
                kfl[2*g+1][0] = r4[1]; kfl[2*g+1][1] = r4[3];
            }
            #pragma unroll
            for (int j = 0; j < 8; j++) {
                mma_bf16(sf[j], qfh[t], kfh[j]);
                mma_bf16(sf[j], qfh[t], kfl[j]);
                mma_bf16(sf[j], qfl[t], kfh[j]);
            }
        }

        // ---- online softmax ----
        float tm0 = -1e30f, tm1 = -1e30f;
        #pragma unroll
        for (int j = 0; j < 8; j++) {
            tm0 = fmaxf(tm0, fmaxf(sf[j][0], sf[j][1]));
            tm1 = fmaxf(tm1, fmaxf(sf[j][2], sf[j][3]));
        }
        tm0 = fmaxf(tm0, __shfl_xor_sync(0xffffffffu, tm0, 1));
        tm0 = fmaxf(tm0, __shfl_xor_sync(0xffffffffu, tm0, 2));
        tm1 = fmaxf(tm1, __shfl_xor_sync(0xffffffffu, tm1, 1));
        tm1 = fmaxf(tm1, __shfl_xor_sync(0xffffffffu, tm1, 2));
        float mn0 = fmaxf(mrow0, tm0), mn1 = fmaxf(mrow1, tm1);
        float cor0 = __expf(mrow0 - mn0), cor1 = __expf(mrow1 - mn1);
        float rs0 = 0.f, rs1 = 0.f;
        #pragma unroll
        for (int j = 0; j < 8; j++) {
            sf[j][0] = __expf(sf[j][0] - mn0);
            sf[j][1] = __expf(sf[j][1] - mn0);
            sf[j][2] = __expf(sf[j][2] - mn1);
            sf[j][3] = __expf(sf[j][3] - mn1);
            rs0 += sf[j][0] + sf[j][1];
            rs1 += sf[j][2] + sf[j][3];
        }
        rs0 += __shfl_xor_sync(0xffffffffu, rs0, 1);
        rs0 += __shfl_xor_sync(0xffffffffu, rs0, 2);
        rs1 += __shfl_xor_sync(0xffffffffu, rs1, 1);
        rs1 += __shfl_xor_sync(0xffffffffu, rs1, 2);
        lrow0 = lrow0 * cor0 + rs0;
        lrow1 = lrow1 * cor1 + rs1;
        mrow0 = mn0; mrow1 = mn1;
        #pragma unroll
        for (int j = 0; j < 8; j++) {
            of[j][0] *= cor0; of[j][1] *= cor0;
            of[j][2] *= cor1; of[j][3] *= cor1;
        }

        // ---- P -> bf16 hi/lo fragments ----
        uint32_t ph[4][4], pl[4][4];
        #pragma unroll
        for (int t = 0; t < 4; t++) {
            #pragma unroll
            for (int half = 0; half < 2; half++) {
                const float* p2 = sf[2 * t + half];
                __nv_bfloat16 h0 = __float2bfloat16(p2[0]);
                __nv_bfloat16 h1 = __float2bfloat16(p2[1]);
                __nv_bfloat16 h2 = __float2bfloat16(p2[2]);
                __nv_bfloat16 h3 = __float2bfloat16(p2[3]);
                ph[t][2 * half + 0] = pack2bf(p2[0], p2[1]);
                ph[t][2 * half + 1] = pack2bf(p2[2], p2[3]);
                pl[t][2 * half + 0] = pack2bf(p2[0] - __bfloat162float(h0),
                                              p2[1] - __bfloat162float(h1));
                pl[t][2 * half + 1] = pack2bf(p2[2] - __bfloat162float(h2),
                                              p2[3] - __bfloat162float(h3));
            }
        }

        // ---- O += P V ----
        #pragma unroll
        for (int t = 0; t < 4; t++) {
            uint32_t vfh[8][2], vfl[8][2];
            #pragma unroll
            for (int g = 0; g < 4; g++) {
                uint32_t r4[4];
                uint32_t ad = vbuf + (t * 16 + v_r) * AT_RB + g * 32 + v_c;
                ldsm_x4_t(r4, ad);
                vfh[2*g][0] = r4[0]; vfh[2*g][1] = r4[1];
                vfh[2*g+1][0] = r4[2]; vfh[2*g+1][1] = r4[3];
                ldsm_x4_t(r4, ad + 9216);
                vfl[2*g][0] = r4[0]; vfl[2*g][1] = r4[1];
                vfl[2*g+1][0] = r4[2]; vfl[2*g+1][1] = r4[3];
            }
            #pragma unroll
            for (int j = 0; j < 8; j++) {
                mma_bf16(of[j], ph[t], vfh[j]);
                mma_bf16(of[j], ph[t], vfl[j]);
                mma_bf16(of[j], pl[t], vfh[j]);
            }
        }
    }

    // ---- epilogue ----
    const float inv0 = 1.f / lrow0, inv1 = 1.f / lrow1;
    const int r0 = q0 + wq + (lane >> 2), r1 = r0 + 8;
    const int b_ = bh >> 4, h_ = bh & 15;
    #pragma unroll
    for (int j = 0; j < 8; j++) {
        int d = j * 8 + (lane & 3) * 2;
        float a0 = of[j][0] * inv0, a1 = of[j][1] * inv0;
        float a2 = of[j][2] * inv1, a3 = of[j][3] * inv1;
        size_t i0 = ((size_t)b_ * SEQ + r0) * DMODEL + h_ * 64 + d;
        size_t i1 = ((size_t)b_ * SEQ + r1) * DMODEL + h_ * 64 + d;
        __nv_bfloat16 h0 = __float2bfloat16(a0), h1 = __float2bfloat16(a1);
        __nv_bfloat16 h2 = __float2bfloat16(a2), h3 = __float2bfloat16(a3);
        *(uint32_t*)(Ohi + i0) = pack2bf(a0, a1);
        *(uint32_t*)(Olo + i0) = pack2bf(a0 - __bfloat162float(h0),
                                         a1 - __bfloat162float(h1));
        *(uint32_t*)(Ohi + i1) = pack2bf(a2, a3);
        *(uint32_t*)(Olo + i1) = pack2bf(a2 - __bfloat162float(h2),
                                         a3 - __bfloat162float(h3));
    }
}

// ---------------------------------------------------------------------------
// Launch
// ---------------------------------------------------------------------------
extern "C" void kernel_launch(void* const* d_in, const int* in_sizes, int n_in,
                              void* d_out, int out_size)
{
    const float* x  = (const float*)d_in[0];
    const float* wq = (const float*)d_in[1];
    const float* bq = (const float*)d_in[2];
    const float* wk = (const float*)d_in[3];
    const float* bk = (const float*)d_in[4];
    const float* wv = (const float*)d_in[5];
    const float* bv = (const float*)d_in[6];
    const float* wo = (const float*)d_in[7];
    const float* bo = (const float*)d_in[8];
    float* out = (float*)d_out;

    __nv_bfloat16 *xhi, *xlo, *qkvhi, *qkvlo, *aohi, *aolo, *wthi, *wtlo;
    float* bias3;
    cudaGetSymbolAddress((void**)&xhi,   g_xhi);
    cudaGetSymbolAddress((void**)&xlo,   g_xlo);
    cudaGetSymbolAddress((void**)&qkvhi, g_qkvhi);
    cudaGetSymbolAddress((void**)&qkvlo, g_qkvlo);
    cudaGetSymbolAddress((void**)&aohi,  g_aohi);
    cudaGetSymbolAddress((void**)&aolo,  g_aolo);
    cudaGetSymbolAddress((void**)&wthi,  g_wthi);
    cudaGetSymbolAddress((void**)&wtlo,  g_wtlo);
    cudaGetSymbolAddress((void**)&bias3, g_bias);

    cudaFuncSetAttribute(gemm_mma2,
                         cudaFuncAttributeMaxDynamicSharedMemorySize, GEMM2_SMEM);
    cudaFuncSetAttribute(attn_mma,
                         cudaFuncAttributeMaxDynamicSharedMemorySize, AT_SMEM);

    // 1. prep: split x, transpose/split weights, concat bias
    int n4 = PSZ / 4;
    split_kernel<<<(n4 + 255) / 256, 256>>>(x, xhi, xlo, n4);
    dim3 tgrid(DMODEL / 32, DMODEL / 32);
    wtrans_kernel<<<tgrid, 256>>>(wq, wthi + 0 * WSZ, wtlo + 0 * WSZ);
    wtrans_kernel<<<tgrid, 256>>>(wk, wthi + 1 * WSZ, wtlo + 1 * WSZ);
    wtrans_kernel<<<tgrid, 256>>>(wv, wthi + 2 * WSZ, wtlo + 2 * WSZ);
    wtrans_kernel<<<tgrid, 256>>>(wo, wthi + 3 * WSZ, wtlo + 3 * WSZ);
    bias_concat<<<(DMODEL + 255) / 256, 256>>>(bq, bk, bv, bias3);

    // 2. fused QKV projection (N=3072)
    dim3 qkv_grid(3 * DMODEL / 256, MROWS / 128);   // (12, 64)
    gemm_mma2<<<qkv_grid, 256, GEMM2_SMEM>>>(
        xhi, xlo, wthi, wtlo, bias3, qkvhi, qkvlo, nullptr, 0);

    // 3. attention
    dim3 agrid(SEQ / 128, BATCH * HEADS);   // (16, 64)
    attn_mma<<<agrid, 256, AT_SMEM>>>(
        qkvhi, qkvlo, qkvhi + PSZ, qkvlo + PSZ, qkvhi + 2 * PSZ, qkvlo + 2 * PSZ,
        aohi, aolo);

    // 4. final projection (N=1024) -> fp32 out
    dim3 ogrid(DMODEL / 256, MROWS / 128);   // (4, 64)
    gemm_mma2<<<ogrid, 256, GEMM2_SMEM>>>(
        aohi, aolo, wthi + 3 * WSZ, wtlo + 3 * WSZ, bo, nullptr, nullptr, out, 1);
}

// round 7
// speedup vs baseline: 5.5708x; 1.8069x over previous
#include <cuda_runtime.h>
#include <cuda_bf16.h>
#include <cuda_fp16.h>
#include <cstdint>

// ---------------------------------------------------------------------------
// MultiHeadAttention: B=4, S=2048, D=1024, H=16, Dk=64, fp32.
// Round 7: precision re-budget. fp16 1-term mma for projections + PV,
// bf16 3-term kept only for QK^T. 412 -> 137.5 GF of mma work.
// ---------------------------------------------------------------------------

#define BATCH 4
#define SEQ   2048
#define DMODEL 1024
#define HEADS 16
#define DK    64
#define MROWS (BATCH * SEQ)          // 8192
#define WSZ   (DMODEL * DMODEL)
#define PSZ   (MROWS * DMODEL)

// ---------------- scratch ----------------------------------------------------
__device__ __align__(128) __half g_xh[PSZ];                  // x fp16
__device__ __align__(128) __half g_wt[4 * WSZ];              // W^T fp16: q,k,v,o
__device__ __align__(128) __nv_bfloat16 g_qkhi[2 * PSZ];     // q,k bf16 hi [bh,s,d]
__device__ __align__(128) __nv_bfloat16 g_qklo[2 * PSZ];     // q,k bf16 lo
__device__ __align__(128) __half g_vh[PSZ];                  // v fp16 [bh,s,d]
__device__ __align__(128) __half g_aoh[PSZ];                 // attn out fp16 [B,S,D]
__device__ __align__(128) float g_bias[3 * DMODEL];

// ---------------- PTX helpers ------------------------------------------------
__device__ __forceinline__ uint32_t smem_u32(const void* p) {
    uint32_t a;
    asm("{ .reg .u64 t; cvta.to.shared.u64 t, %1; cvt.u32.u64 %0, t; }"
        : "=r"(a) : "l"(p));
    return a;
}
__device__ __forceinline__ void ldsm_x4(uint32_t* r, uint32_t addr) {
    asm volatile("ldmatrix.sync.aligned.m8n8.x4.shared.b16 {%0,%1,%2,%3}, [%4];"
        : "=r"(r[0]), "=r"(r[1]), "=r"(r[2]), "=r"(r[3]) : "r"(addr));
}
__device__ __forceinline__ void ldsm_x4_t(uint32_t* r, uint32_t addr) {
    asm volatile("ldmatrix.sync.aligned.m8n8.x4.trans.shared.b16 {%0,%1,%2,%3}, [%4];"
        : "=r"(r[0]), "=r"(r[1]), "=r"(r[2]), "=r"(r[3]) : "r"(addr));
}
__device__ __forceinline__ void mma_bf16(float* c, const uint32_t* a, const uint32_t* b) {
    asm volatile(
        "mma.sync.aligned.m16n8k16.row.col.f32.bf16.bf16.f32 "
        "{%0,%1,%2,%3}, {%4,%5,%6,%7}, {%8,%9}, {%0,%1,%2,%3};"
        : "+f"(c[0]), "+f"(c[1]), "+f"(c[2]), "+f"(c[3])
        : "r"(a[0]), "r"(a[1]), "r"(a[2]), "r"(a[3]), "r"(b[0]), "r"(b[1]));
}
__device__ __forceinline__ void mma_f16(float* c, const uint32_t* a, const uint32_t* b) {
    asm volatile(
        "mma.sync.aligned.m16n8k16.row.col.f32.f16.f16.f32 "
        "{%0,%1,%2,%3}, {%4,%5,%6,%7}, {%8,%9}, {%0,%1,%2,%3};"
        : "+f"(c[0]), "+f"(c[1]), "+f"(c[2]), "+f"(c[3])
        : "r"(a[0]), "r"(a[1]), "r"(a[2]), "r"(a[3]), "r"(b[0]), "r"(b[1]));
}
#define CP_ASYNC16(dst, src) \
    asm volatile("cp.async.cg.shared.global [%0], [%1], 16;" \
                 :: "r"(dst), "l"(src))
#define CP_COMMIT() asm volatile("cp.async.commit_group;" ::: "memory")
#define CP_WAIT(n)  asm volatile("cp.async.wait_group %0;" :: "n"(n) : "memory")

__device__ __forceinline__ uint32_t pack2bf(float a, float b) {
    __nv_bfloat162 t = __floats2bfloat162_rn(a, b);
    return *(uint32_t*)&t;
}
__device__ __forceinline__ uint32_t pack2h(float a, float b) {
    __half2 t = __floats2half2_rn(a, b);
    return *(uint32_t*)&t;
}

// ---------------- prep kernels -------------------------------------------------
__global__ __launch_bounds__(256) void x_to_h(
    const float* __restrict__ in, __half* __restrict__ out, int n4)
{
    int i = blockIdx.x * 256 + threadIdx.x;
    if (i >= n4) return;
    float4 v = ((const float4*)in)[i];
    uint2 o;
    o.x = pack2h(v.x, v.y);
    o.y = pack2h(v.z, v.w);
    ((uint2*)out)[i] = o;
}

__global__ __launch_bounds__(256) void wtrans_kernel(
    const float* __restrict__ W, __half* __restrict__ T)
{
    __shared__ float tile[32][33];
    const int n0 = blockIdx.x * 32, k0 = blockIdx.y * 32;
    const int tx = threadIdx.x & 31, ty = threadIdx.x >> 5;
    #pragma unroll
    for (int r = 0; r < 4; r++)
        tile[ty + 8 * r][tx] = W[(size_t)(k0 + ty + 8 * r) * DMODEL + n0 + tx];
    __syncthreads();
    #pragma unroll
    for (int r = 0; r < 4; r++) {
        int n = n0 + ty + 8 * r, k = k0 + tx;
        T[(size_t)n * DMODEL + k] = __float2half(tile[tx][ty + 8 * r]);
    }
}

__global__ void bias_concat(const float* bq, const float* bk, const float* bv,
                            float* dst)
{
    int i = blockIdx.x * 256 + threadIdx.x;
    if (i < DMODEL) {
        dst[i] = bq[i];
        dst[DMODEL + i] = bk[i];
        dst[2 * DMODEL + i] = bv[i];
    }
}

// ---------------- fp16 1-term GEMM (128m x 256n CTA, 64x64 warp, BK=64) -------
// mode 0: fused QKV (N=3072): q,k -> bf16 hi/lo scatter (q scaled 1/8),
//         v -> fp16 scatter.
// mode 1: final projection (N=1024): fp32 row-major out.
#define BK3 64
#define ROW3 144
#define A_T3 (128 * ROW3)          // 18432
#define B_T3 (256 * ROW3)          // 36864
#define STG3 (A_T3 + B_T3)         // 55296
#define G3_SMEM (3 * STG3)         // 165888
#define NCH3 (DMODEL / BK3)        // 16

__global__ __launch_bounds__(256, 1) void gemm_h(
    const __half* __restrict__ A, const __half* __restrict__ B,
    const float* __restrict__ bias,
    __nv_bfloat16* __restrict__ qkhi, __nv_bfloat16* __restrict__ qklo,
    __half* __restrict__ vh, float* __restrict__ ofp, int mode)
{
    extern __shared__ char smem[];
    const uint32_t sbase = smem_u32(smem);
    const int tid = threadIdx.x;
    const int wid = tid >> 5, lane = tid & 31;
    const int n0 = blockIdx.x * 256;
    const int m0 = blockIdx.y * 128;

    const int warp_m = (wid & 1) * 64;
    const int warp_n = (wid >> 1) * 64;

    const __half* gA = A + (size_t)m0 * DMODEL;
    const __half* gB = B + (size_t)n0 * DMODEL;

    auto load_stage = [&](int st, int c) {
        const int k0 = c * BK3;
        const uint32_t stage = sbase + st * STG3;
        #pragma unroll
        for (int i = 0; i < 4; i++) {                    // A: 128 x 8ch
            int idx = tid + i * 256;
            int row = idx >> 3, ch = idx & 7;
            CP_ASYNC16(stage + row * ROW3 + ch * 16,
                       gA + (size_t)row * DMODEL + k0 + ch * 8);
        }
        #pragma unroll
        for (int i = 0; i < 8; i++) {                    // B: 256 x 8ch
            int idx = tid + i * 256;
            int row = idx >> 3, ch = idx & 7;
            CP_ASYNC16(stage + A_T3 + row * ROW3 + ch * 16,
                       gB + (size_t)row * DMODEL + k0 + ch * 8);
        }
    };

    float acc[4][8][4];
    #pragma unroll
    for (int i = 0; i < 4; i++)
        #pragma unroll
        for (int j = 0; j < 8; j++)
            #pragma unroll
            for (int q = 0; q < 4; q++) acc[i][j][q] = 0.f;

    load_stage(0, 0); CP_COMMIT();
    load_stage(1, 1); CP_COMMIT();

    const int a_r = lane & 15;
    const int a_c = (lane & 16) ? 16 : 0;
    const int b_r = ((lane & 16) ? 8 : 0) + (lane & 7);
    const int b_c = (lane & 8) ? 16 : 0;

    for (int c = 0; c < NCH3; c++) {
        if (c + 2 < NCH3) { CP_WAIT(1); } else { CP_WAIT(0); }
        __syncthreads();
        if (c + 2 < NCH3) { load_stage((c + 2) % 3, c + 2); CP_COMMIT(); }

        const uint32_t stage = sbase + (c % 3) * STG3;

        #pragma unroll
        for (int ks = 0; ks < 4; ks++) {
            uint32_t ah[4][4];
            #pragma unroll
            for (int mf = 0; mf < 4; mf++)
                ldsm_x4(ah[mf], stage + (warp_m + mf * 16 + a_r) * ROW3
                                 + ks * 32 + a_c);
            #pragma unroll
            for (int nfp = 0; nfp < 4; nfp++) {
                uint32_t bh[4];
                ldsm_x4(bh, stage + A_T3 + (warp_n + nfp * 16 + b_r) * ROW3
                             + ks * 32 + b_c);
                #pragma unroll
                for (int mf = 0; mf < 4; mf++) {
                    mma_f16(acc[mf][nfp * 2 + 0], ah[mf], bh + 0);
                    mma_f16(acc[mf][nfp * 2 + 1], ah[mf], bh + 2);
                }
            }
        }
    }

    // ---- epilogue ----
    #pragma unroll
    for (int mf = 0; mf < 4; mf++) {
        const int mA = m0 + warp_m + mf * 16 + (lane >> 2);
        #pragma unroll
        for (int nf = 0; nf < 8; nf++) {
            const int n = n0 + warp_n + nf * 8 + (lane & 3) * 2;
            const float b0 = bias[n], b1 = bias[n + 1];
            float v0 = acc[mf][nf][0] + b0;
            float v1 = acc[mf][nf][1] + b1;
            float v2 = acc[mf][nf][2] + b0;
            float v3 = acc[mf][nf][3] + b1;
            if (mode == 0) {
                int proj = n >> 10;
                int np = n & 1023;
                int h = np >> 6, d = np & 63;
                int bb0 = mA >> 11, s0 = mA & 2047;
                int m2 = mA + 8;
                int bb1 = m2 >> 11, s1 = m2 & 2047;
                size_t i0 = ((size_t)(bb0 * HEADS + h) * SEQ + s0) * DK + d;
                size_t i1 = ((size_t)(bb1 * HEADS + h) * SEQ + s1) * DK + d;
                if (proj < 2) {
                    if (proj == 0) { v0 *= 0.125f; v1 *= 0.125f; v2 *= 0.125f; v3 *= 0.125f; }
                    size_t off = (size_t)proj * PSZ;
                    __nv_bfloat16 h0 = __float2bfloat16(v0), h1 = __float2bfloat16(v1);
                    __nv_bfloat16 h2 = __float2bfloat16(v2), h3 = __float2bfloat16(v3);
                    *(uint32_t*)(qkhi + off + i0) = pack2bf(v0, v1);
                    *(uint32_t*)(qklo + off + i0) = pack2bf(v0 - __bfloat162float(h0),
                                                            v1 - __bfloat162float(h1));
                    *(uint32_t*)(qkhi + off + i1) = pack2bf(v2, v3);
                    *(uint32_t*)(qklo + off + i1) = pack2bf(v2 - __bfloat162float(h2),
                                                            v3 - __bfloat162float(h3));
                } else {
                    *(uint32_t*)(vh + i0) = pack2h(v0, v1);
                    *(uint32_t*)(vh + i1) = pack2h(v2, v3);
                }
            } else {
                float2 w0 = {v0, v1}, w1 = {v2, v3};
                *(float2*)(ofp + (size_t)mA * DMODEL + n) = w0;
                *(float2*)(ofp + (size_t)(mA + 8) * DMODEL + n) = w1;
            }
        }
    }
}

// ---------------- HMMA flash attention ---------------------------------------
// QK: bf16 3-term (Q,K hi/lo). PV: fp16 1-term (P packed fp16, V fp16).
// 4-stage cp.async pipeline, 1 sync per KV tile.
#define AT_RB 144
#define AT_QH 0u
#define AT_QL 18432u
#define AT_STG 36864u            // + st*27648: Kh, Kl(+9216), V(+18432)
#define AT_STGB 27648
#define AT_SMEM (36864 + 4 * AT_STGB)   // 147456

__global__ __launch_bounds__(256, 1) void attn_mma(
    const __nv_bfloat16* __restrict__ Qh, const __nv_bfloat16* __restrict__ Ql,
    const __nv_bfloat16* __restrict__ Kh, const __nv_bfloat16* __restrict__ Kl,
    const __half* __restrict__ V, __half* __restrict__ Ao)
{
    extern __shared__ char smem[];
    const uint32_t sb = smem_u32(smem);
    const int tid = threadIdx.x, wid = tid >> 5, lane = tid & 31;
    const int qt = blockIdx.x, bh = blockIdx.y;
    const int q0 = qt * 128;
    const size_t base = (size_t)bh * SEQ * DK;

    const char* kv_src[3] = {
        (const char*)(Kh + base), (const char*)(Kl + base), (const char*)(V + base) };

    auto ld_q = [&] {
        #pragma unroll
        for (int i = 0; i < 8; i++) {
            int idx = tid + i * 256;
            int hl = idx >> 10;
            int r  = (idx >> 3) & 127;
            int ch = idx & 7;
            const __nv_bfloat16* src = (hl ? Ql : Qh) + base + (size_t)(q0 + r) * DK + ch * 8;
            CP_ASYNC16(sb + (hl ? AT_QL : AT_QH) + r * AT_RB + ch * 16, src);
        }
    };
    auto ld_kv = [&](int st, int t) {
        #pragma unroll
        for (int i = 0; i < 6; i++) {
            int idx = tid + i * 256;              // 0..1535
            int ts = idx >> 9;                    // 0 kh, 1 kl, 2 v
            int r  = (idx >> 3) & 63;
            int ch = idx & 7;
            const char* sp = kv_src[ts] + (size_t)(t * 64 + r) * 128 + ch * 16;
            CP_ASYNC16(sb + AT_STG + st * AT_STGB + ts * 9216 + r * AT_RB + ch * 16, sp);
        }
    };

    ld_q(); ld_kv(0, 0); CP_COMMIT();
    ld_kv(1, 1); CP_COMMIT();
    ld_kv(2, 2); CP_COMMIT();

    const int a_r = lane & 15;
    const int a_c = (lane & 16) ? 16 : 0;
    const int bm = lane >> 3;
    const int b_r = (bm & 1) * 8 + (lane & 7);
    const int b_c = (bm >> 1) * 16;
    const int v_r = lane & 15;
    const int v_c = (lane & 16) ? 16 : 0;

    const int wq = wid * 16;
    uint32_t qfh[4][4], qfl[4][4];

    float of[8][4];
    #pragma unroll
    for (int j = 0; j < 8; j++)
        #pragma unroll
        for (int q = 0; q < 4; q++) of[j][q] = 0.f;
    float mrow0 = -1e30f, mrow1 = -1e30f, lrow0 = 0.f, lrow1 = 0.f;

    for (int c = 0; c < 32; c++) {
        if (c + 3 < 32) { CP_WAIT(2); } else { CP_WAIT(0); }
        __syncthreads();
        if (c == 0) {
            #pragma unroll
            for (int t = 0; t < 4; t++) {
                ldsm_x4(qfh[t], sb + AT_QH + (wq + a_r) * AT_RB + t * 32 + a_c);
                ldsm_x4(qfl[t], sb + AT_QL + (wq + a_r) * AT_RB + t * 32 + a_c);
            }
        }
        if (c + 3 < 32) { ld_kv((c + 3) & 3, c + 3); CP_COMMIT(); }

        const uint32_t kbuf = sb + AT_STG + (c & 3) * AT_STGB;
        const uint32_t vbuf = kbuf + 18432;

        // ---- S = Q K^T (bf16 3-term) ----
        float sf[8][4];
        #pragma unroll
        for (int j = 0; j < 8; j++)
            #pragma unroll
            for (int q = 0; q < 4; q++) sf[j][q] = 0.f;

        #pragma unroll
        for (int t = 0; t < 4; t++) {
            uint32_t kfh[8][2], kfl[8][2];
            #pragma unroll
            for (int g = 0; g < 4; g++) {
                uint32_t r4[4];
                uint32_t ad = kbuf + (g * 16 + b_r) * AT_RB + t * 32 + b_c;
                ldsm_x4(r4, ad);
                kfh[2*g][0] = r4[0]; kfh[2*g][1] = r4[2];
                kfh[2*g+1][0] = r4[1]; kfh[2*g+1][1] = r4[3];
                ldsm_x4(r4, ad + 9216);
                kfl[2*g][0] = r4[0]; kfl[2*g][1] = r4[2];
                kfl[2*g+1][0] = r4[1]; kfl[2*g+1][1] = r4[3];
            }
            #pragma unroll
            for (int j = 0; j < 8; j++) {
                mma_bf16(sf[j], qfh[t], kfh[j]);
                mma_bf16(sf[j], qfh[t], kfl[j]);
                mma_bf16(sf[j], qfl[t], kfh[j]);
            }
        }

        // ---- online softmax ----
        float tm0 = -1e30f, tm1 = -1e30f;
        #pragma unroll
        for (int j = 0; j < 8; j++) {
            tm0 = fmaxf(tm0, fmaxf(sf[j][0], sf[j][1]));
            tm1 = fmaxf(tm1, fmaxf(sf[j][2], sf[j][3]));
        }
        tm0 = fmaxf(tm0, __shfl_xor_sync(0xffffffffu, tm0, 1));
        tm0 = fmaxf(tm0, __shfl_xor_sync(0xffffffffu, tm0, 2));
        tm1 = fmaxf(tm1, __shfl_xor_sync(0xffffffffu, tm1, 1));
        tm1 = fmaxf(tm1, __shfl_xor_sync(0xffffffffu, tm1, 2));
        float mn0 = fmaxf(mrow0, tm0), mn1 = fmaxf(mrow1, tm1);
        float cor0 = __expf(mrow0 - mn0), cor1 = __expf(mrow1 - mn1);
        float rs0 = 0.f, rs1 = 0.f;
        #pragma unroll
        for (int j = 0; j < 8; j++) {
            sf[j][0] = __expf(sf[j][0] - mn0);
            sf[j][1] = __expf(sf[j][1] - mn0);
            sf[j][2] = __expf(sf[j][2] - mn1);
            sf[j][3] = __expf(sf[j][3] - mn1);
            rs0 += sf[j][0] + sf[j][1];
            rs1 += sf[j][2] + sf[j][3];
        }
        rs0 += __shfl_xor_sync(0xffffffffu, rs0, 1);
        rs0 += __shfl_xor_sync(0xffffffffu, rs0, 2);
        rs1 += __shfl_xor_sync(0xffffffffu, rs1, 1);
        rs1 += __shfl_xor_sync(0xffffffffu, rs1, 2);
        lrow0 = lrow0 * cor0 + rs0;
        lrow1 = lrow1 * cor1 + rs1;
        mrow0 = mn0; mrow1 = mn1;
        #pragma unroll
        for (int j = 0; j < 8; j++) {
            of[j][0] *= cor0; of[j][1] *= cor0;
            of[j][2] *= cor1; of[j][3] *= cor1;
        }

        // ---- P -> fp16 fragments ----
        uint32_t ph[4][4];
        #pragma unroll
        for (int t = 0; t < 4; t++) {
            #pragma unroll
            for (int half = 0; half < 2; half++) {
                const float* p2 = sf[2 * t + half];
                ph[t][2 * half + 0] = pack2h(p2[0], p2[1]);
                ph[t][2 * half + 1] = pack2h(p2[2], p2[3]);
            }
        }

        // ---- O += P V (fp16 1-term) ----
        #pragma unroll
        for (int t = 0; t < 4; t++) {
            uint32_t vf[8][2];
            #pragma unroll
            for (int g = 0; g < 4; g++) {
                uint32_t r4[4];
                ldsm_x4_t(r4, vbuf + (t * 16 + v_r) * AT_RB + g * 32 + v_c);
                vf[2*g][0] = r4[0]; vf[2*g][1] = r4[1];
                vf[2*g+1][0] = r4[2]; vf[2*g+1][1] = r4[3];
            }
            #pragma unroll
            for (int j = 0; j < 8; j++)
                mma_f16(of[j], ph[t], vf[j]);
        }
    }

    // ---- epilogue: fp16 out [B, S, H*Dk] ----
    const float inv0 = 1.f / lrow0, inv1 = 1.f / lrow1;
    const int r0 = q0 + wq + (lane >> 2), r1 = r0 + 8;
    const int b_ = bh >> 4, h_ = bh & 15;
    #pragma unroll
    for (int j = 0; j < 8; j++) {
        int d = j * 8 + (lane & 3) * 2;
        size_t i0 = ((size_t)b_ * SEQ + r0) * DMODEL + h_ * 64 + d;
        size_t i1 = ((size_t)b_ * SEQ + r1) * DMODEL + h_ * 64 + d;
        *(uint32_t*)(Ao + i0) = pack2h(of[j][0] * inv0, of[j][1] * inv0);
        *(uint32_t*)(Ao + i1) = pack2h(of[j][2] * inv1, of[j][3] * inv1);
    }
}

// ---------------------------------------------------------------------------
// Launch
// ---------------------------------------------------------------------------
extern "C" void kernel_launch(void* const* d_in, const int* in_sizes, int n_in,
                              void* d_out, int out_size)
{
    const float* x  = (const float*)d_in[0];
    const float* wq = (const float*)d_in[1];
    const float* bq = (const float*)d_in[2];
    const float* wk = (const float*)d_in[3];
    const float* bk = (const float*)d_in[4];
    const float* wv = (const float*)d_in[5];
    const float* bv = (const float*)d_in[6];
    const float* wo = (const float*)d_in[7];
    const float* bo = (const float*)d_in[8];
    float* out = (float*)d_out;

    __half *xh, *wt, *vh, *aoh;
    __nv_bfloat16 *qkhi, *qklo;
    float* bias3;
    cudaGetSymbolAddress((void**)&xh,    g_xh);
    cudaGetSymbolAddress((void**)&wt,    g_wt);
    cudaGetSymbolAddress((void**)&qkhi,  g_qkhi);
    cudaGetSymbolAddress((void**)&qklo,  g_qklo);
    cudaGetSymbolAddress((void**)&vh,    g_vh);
    cudaGetSymbolAddress((void**)&aoh,   g_aoh);
    cudaGetSymbolAddress((void**)&bias3, g_bias);

    cudaFuncSetAttribute(gemm_h,
                         cudaFuncAttributeMaxDynamicSharedMemorySize, G3_SMEM);
    cudaFuncSetAttribute(attn_mma,
                         cudaFuncAttributeMaxDynamicSharedMemorySize, AT_SMEM);

    // 1. prep
    int n4 = PSZ / 4;
    x_to_h<<<(n4 + 255) / 256, 256>>>(x, xh, n4);
    dim3 tgrid(DMODEL / 32, DMODEL / 32);
    wtrans_kernel<<<tgrid, 256>>>(wq, wt + 0 * WSZ);
    wtrans_kernel<<<tgrid, 256>>>(wk, wt + 1 * WSZ);
    wtrans_kernel<<<tgrid, 256>>>(wv, wt + 2 * WSZ);
    wtrans_kernel<<<tgrid, 256>>>(wo, wt + 3 * WSZ);
    bias_concat<<<(DMODEL + 255) / 256, 256>>>(bq, bk, bv, bias3);

    // 2. fused QKV projection (fp16 1-term, N=3072)
    dim3 qkv_grid(3 * DMODEL / 256, MROWS / 128);   // (12, 64)
    gemm_h<<<qkv_grid, 256, G3_SMEM>>>(xh, wt, bias3, qkhi, qklo, vh, nullptr, 0);

    // 3. attention
    dim3 agrid(SEQ / 128, BATCH * HEADS);   // (16, 64)
    attn_mma<<<agrid, 256, AT_SMEM>>>(qkhi, qklo, qkhi + PSZ, qklo + PSZ, vh, aoh);

    // 4. final projection (fp16 1-term, N=1024) -> fp32 out
    dim3 ogrid(DMODEL / 256, MROWS / 128);   // (4, 64)
    gemm_h<<<ogrid, 256, G3_SMEM>>>(aoh, wt + 3 * WSZ, bo, nullptr, nullptr,
                                    nullptr, out, 1);
}

// round 8
// speedup vs baseline: 7.5526x; 1.3557x over previous
#include <cuda_runtime.h>
#include <cuda_fp16.h>
#include <cstdint>

// ---------------------------------------------------------------------------
// MultiHeadAttention: B=4, S=2048, D=1024, H=16, Dk=64, fp32.
// Round 8: all-fp16 operands (fp32 accum) everywhere. QK^T dropped from
// bf16 3-term to fp16 1-term. Total mma work 206 -> 137.5 GF.
// ---------------------------------------------------------------------------

#define BATCH 4
#define SEQ   2048
#define DMODEL 1024
#define HEADS 16
#define DK    64
#define MROWS (BATCH * SEQ)          // 8192
#define WSZ   (DMODEL * DMODEL)
#define PSZ   (MROWS * DMODEL)

// ---------------- scratch ----------------------------------------------------
__device__ __align__(128) __half g_xh[PSZ];                  // x fp16
__device__ __align__(128) __half g_wt[4 * WSZ];              // W^T fp16: q,k,v,o
__device__ __align__(128) __half g_qkv[3 * PSZ];             // q,k,v fp16 [bh,s,d]
__device__ __align__(128) __half g_aoh[PSZ];                 // attn out fp16 [B,S,D]
__device__ __align__(128) float g_bias[3 * DMODEL];

// ---------------- PTX helpers ------------------------------------------------
__device__ __forceinline__ uint32_t smem_u32(const void* p) {
    uint32_t a;
    asm("{ .reg .u64 t; cvta.to.shared.u64 t, %1; cvt.u32.u64 %0, t; }"
        : "=r"(a) : "l"(p));
    return a;
}
__device__ __forceinline__ void ldsm_x4(uint32_t* r, uint32_t addr) {
    asm volatile("ldmatrix.sync.aligned.m8n8.x4.shared.b16 {%0,%1,%2,%3}, [%4];"
        : "=r"(r[0]), "=r"(r[1]), "=r"(r[2]), "=r"(r[3]) : "r"(addr));
}
__device__ __forceinline__ void ldsm_x4_t(uint32_t* r, uint32_t addr) {
    asm volatile("ldmatrix.sync.aligned.m8n8.x4.trans.shared.b16 {%0,%1,%2,%3}, [%4];"
        : "=r"(r[0]), "=r"(r[1]), "=r"(r[2]), "=r"(r[3]) : "r"(addr));
}
__device__ __forceinline__ void mma_f16(float* c, const uint32_t* a, const uint32_t* b) {
    asm volatile(
        "mma.sync.aligned.m16n8k16.row.col.f32.f16.f16.f32 "
        "{%0,%1,%2,%3}, {%4,%5,%6,%7}, {%8,%9}, {%0,%1,%2,%3};"
        : "+f"(c[0]), "+f"(c[1]), "+f"(c[2]), "+f"(c[3])
        : "r"(a[0]), "r"(a[1]), "r"(a[2]), "r"(a[3]), "r"(b[0]), "r"(b[1]));
}
#define CP_ASYNC16(dst, src) \
    asm volatile("cp.async.cg.shared.global [%0], [%1], 16;" \
                 :: "r"(dst), "l"(src))
#define CP_COMMIT() asm volatile("cp.async.commit_group;" ::: "memory")
#define CP_WAIT(n)  asm volatile("cp.async.wait_group %0;" :: "n"(n) : "memory")

__device__ __forceinline__ uint32_t pack2h(float a, float b) {
    __half2 t = __floats2half2_rn(a, b);
    return *(uint32_t*)&t;
}

// ---------------- prep kernels -------------------------------------------------
__global__ __launch_bounds__(256) void x_to_h(
    const float* __restrict__ in, __half* __restrict__ out, int n4)
{
    int i = blockIdx.x * 256 + threadIdx.x;
    if (i >= n4) return;
    float4 v = ((const float4*)in)[i];
    uint2 o;
    o.x = pack2h(v.x, v.y);
    o.y = pack2h(v.z, v.w);
    ((uint2*)out)[i] = o;
}

__global__ __launch_bounds__(256) void wtrans_kernel(
    const float* __restrict__ W, __half* __restrict__ T)
{
    __shared__ float tile[32][33];
    const int n0 = blockIdx.x * 32, k0 = blockIdx.y * 32;
    const int tx = threadIdx.x & 31, ty = threadIdx.x >> 5;
    #pragma unroll
    for (int r = 0; r < 4; r++)
        tile[ty + 8 * r][tx] = W[(size_t)(k0 + ty + 8 * r) * DMODEL + n0 + tx];
    __syncthreads();
    #pragma unroll
    for (int r = 0; r < 4; r++) {
        int n = n0 + ty + 8 * r, k = k0 + tx;
        T[(size_t)n * DMODEL + k] = __float2half(tile[tx][ty + 8 * r]);
    }
}

__global__ void bias_concat(const float* bq, const float* bk, const float* bv,
                            float* dst)
{
    int i = blockIdx.x * 256 + threadIdx.x;
    if (i < DMODEL) {
        dst[i] = bq[i];
        dst[DMODEL + i] = bk[i];
        dst[2 * DMODEL + i] = bv[i];
    }
}

// ---------------- fp16 GEMM (128m x 256n CTA, 64x64 warp, BK=64) --------------
// mode 0: fused QKV (N=3072) -> fp16 scatter to g_qkv[proj][bh,s,d], q scaled.
// mode 1: final projection (N=1024) -> fp32 row-major out.
#define BK3 64
#define ROW3 144
#define A_T3 (128 * ROW3)          // 18432
#define B_T3 (256 * ROW3)          // 36864
#define STG3 (A_T3 + B_T3)         // 55296
#define G3_SMEM (3 * STG3)         // 165888
#define NCH3 (DMODEL / BK3)        // 16

__global__ __launch_bounds__(256, 1) void gemm_h(
    const __half* __restrict__ A, const __half* __restrict__ B,
    const float* __restrict__ bias,
    __half* __restrict__ qkv, float* __restrict__ ofp, int mode)
{
    extern __shared__ char smem[];
    const uint32_t sbase = smem_u32(smem);
    const int tid = threadIdx.x;
    const int wid = tid >> 5, lane = tid & 31;
    const int n0 = blockIdx.x * 256;
    const int m0 = blockIdx.y * 128;

    const int warp_m = (wid & 1) * 64;
    const int warp_n = (wid >> 1) * 64;

    const __half* gA = A + (size_t)m0 * DMODEL;
    const __half* gB = B + (size_t)n0 * DMODEL;

    auto load_stage = [&](int st, int c) {
        const int k0 = c * BK3;
        const uint32_t stage = sbase + st * STG3;
        #pragma unroll
        for (int i = 0; i < 4; i++) {
            int idx = tid + i * 256;
            int row = idx >> 3, ch = idx & 7;
            CP_ASYNC16(stage + row * ROW3 + ch * 16,
                       gA + (size_t)row * DMODEL + k0 + ch * 8);
        }
        #pragma unroll
        for (int i = 0; i < 8; i++) {
            int idx = tid + i * 256;
            int row = idx >> 3, ch = idx & 7;
            CP_ASYNC16(stage + A_T3 + row * ROW3 + ch * 16,
                       gB + (size_t)row * DMODEL + k0 + ch * 8);
        }
    };

    float acc[4][8][4];
    #pragma unroll
    for (int i = 0; i < 4; i++)
        #pragma unroll
        for (int j = 0; j < 8; j++)
            #pragma unroll
            for (int q = 0; q < 4; q++) acc[i][j][q] = 0.f;

    load_stage(0, 0); CP_COMMIT();
    load_stage(1, 1); CP_COMMIT();

    const int a_r = lane & 15;
    const int a_c = (lane & 16) ? 16 : 0;
    const int b_r = ((lane & 16) ? 8 : 0) + (lane & 7);
    const int b_c = (lane & 8) ? 16 : 0;

    for (int c = 0; c < NCH3; c++) {
        if (c + 2 < NCH3) { CP_WAIT(1); } else { CP_WAIT(0); }
        __syncthreads();
        if (c + 2 < NCH3) { load_stage((c + 2) % 3, c + 2); CP_COMMIT(); }

        const uint32_t stage = sbase + (c % 3) * STG3;

        #pragma unroll
        for (int ks = 0; ks < 4; ks++) {
            uint32_t ah[4][4];
            #pragma unroll
            for (int mf = 0; mf < 4; mf++)
                ldsm_x4(ah[mf], stage + (warp_m + mf * 16 + a_r) * ROW3
                                 + ks * 32 + a_c);
            #pragma unroll
            for (int nfp = 0; nfp < 4; nfp++) {
                uint32_t bh[4];
                ldsm_x4(bh, stage + A_T3 + (warp_n + nfp * 16 + b_r) * ROW3
                             + ks * 32 + b_c);
                #pragma unroll
                for (int mf = 0; mf < 4; mf++) {
                    mma_f16(acc[mf][nfp * 2 + 0], ah[mf], bh + 0);
                    mma_f16(acc[mf][nfp * 2 + 1], ah[mf], bh + 2);
                }
            }
        }
    }

    // ---- epilogue ----
    #pragma unroll
    for (int mf = 0; mf < 4; mf++) {
        const int mA = m0 + warp_m + mf * 16 + (lane >> 2);
        #pragma unroll
        for (int nf = 0; nf < 8; nf++) {
            const int n = n0 + warp_n + nf * 8 + (lane & 3) * 2;
            const float b0 = bias[n], b1 = bias[n + 1];
            float v0 = acc[mf][nf][0] + b0;
            float v1 = acc[mf][nf][1] + b1;
            float v2 = acc[mf][nf][2] + b0;
            float v3 = acc[mf][nf][3] + b1;
            if (mode == 0) {
                int proj = n >> 10;
                int np = n & 1023;
                int h = np >> 6, d = np & 63;
                int bb0 = mA >> 11, s0 = mA & 2047;
                int m2 = mA + 8;
                int bb1 = m2 >> 11, s1 = m2 & 2047;
                size_t off = (size_t)proj * PSZ;
                size_t i0 = off + ((size_t)(bb0 * HEADS + h) * SEQ + s0) * DK + d;
                size_t i1 = off + ((size_t)(bb1 * HEADS + h) * SEQ + s1) * DK + d;
                if (proj == 0) { v0 *= 0.125f; v1 *= 0.125f; v2 *= 0.125f; v3 *= 0.125f; }
                *(uint32_t*)(qkv + i0) = pack2h(v0, v1);
                *(uint32_t*)(qkv + i1) = pack2h(v2, v3);
            } else {
                float2 w0 = {v0, v1}, w1 = {v2, v3};
                *(float2*)(ofp + (size_t)mA * DMODEL + n) = w0;
                *(float2*)(ofp + (size_t)(mA + 8) * DMODEL + n) = w1;
            }
        }
    }
}

// ---------------- fp16 HMMA flash attention ------------------------------------
// All fp16 1-term. 4-stage cp.async pipeline, 1 sync per KV tile.
#define AT_RB 144
#define AT_Q  0u
#define AT_STG 18432u            // + st*18432: K, V(+9216)
#define AT_STGB 18432
#define AT_SMEM (18432 + 4 * AT_STGB)   // 92160

__global__ __launch_bounds__(256, 1) void attn_mma(
    const __half* __restrict__ Q, const __half* __restrict__ K,
    const __half* __restrict__ V, __half* __restrict__ Ao)
{
    extern __shared__ char smem[];
    const uint32_t sb = smem_u32(smem);
    const int tid = threadIdx.x, wid = tid >> 5, lane = tid & 31;
    const int qt = blockIdx.x, bh = blockIdx.y;
    const int q0 = qt * 128;
    const size_t base = (size_t)bh * SEQ * DK;

    const char* kv_src[2] = { (const char*)(K + base), (const char*)(V + base) };

    auto ld_q = [&] {
        #pragma unroll
        for (int i = 0; i < 4; i++) {
            int idx = tid + i * 256;              // 0..1023
            int r  = idx >> 3;
            int ch = idx & 7;
            CP_ASYNC16(sb + AT_Q + r * AT_RB + ch * 16,
                       (const char*)(Q + base + (size_t)(q0 + r) * DK) + ch * 16);
        }
    };
    auto ld_kv = [&](int st, int t) {
        #pragma unroll
        for (int i = 0; i < 4; i++) {
            int idx = tid + i * 256;              // 0..1023
            int ts = idx >> 9;                    // 0 k, 1 v
            int r  = (idx >> 3) & 63;
            int ch = idx & 7;
            const char* sp = kv_src[ts] + (size_t)(t * 64 + r) * 128 + ch * 16;
            CP_ASYNC16(sb + AT_STG + st * AT_STGB + ts * 9216 + r * AT_RB + ch * 16, sp);
        }
    };

    ld_q(); ld_kv(0, 0); CP_COMMIT();
    ld_kv(1, 1); CP_COMMIT();
    ld_kv(2, 2); CP_COMMIT();

    const int a_r = lane & 15;
    const int a_c = (lane & 16) ? 16 : 0;
    const int bm = lane >> 3;
    const int b_r = (bm & 1) * 8 + (lane & 7);
    const int b_c = (bm >> 1) * 16;
    const int v_r = lane & 15;
    const int v_c = (lane & 16) ? 16 : 0;

    const int wq = wid * 16;
    uint32_t qf[4][4];

    float of[8][4];
    #pragma unroll
    for (int j = 0; j < 8; j++)
        #pragma unroll
        for (int q = 0; q < 4; q++) of[j][q] = 0.f;
    float mrow0 = -1e30f, mrow1 = -1e30f, lrow0 = 0.f, lrow1 = 0.f;

    for (int c = 0; c < 32; c++) {
        if (c + 3 < 32) { CP_WAIT(2); } else { CP_WAIT(0); }
        __syncthreads();
        if (c == 0) {
            #pragma unroll
            for (int t = 0; t < 4; t++)
                ldsm_x4(qf[t], sb + AT_Q + (wq + a_r) * AT_RB + t * 32 + a_c);
        }
        if (c + 3 < 32) { ld_kv((c + 3) & 3, c + 3); CP_COMMIT(); }

        const uint32_t kbuf = sb + AT_STG + (c & 3) * AT_STGB;
        const uint32_t vbuf = kbuf + 9216;

        // ---- S = Q K^T (fp16 1-term) ----
        float sf[8][4];
        #pragma unroll
        for (int j = 0; j < 8; j++)
            #pragma unroll
            for (int q = 0; q < 4; q++) sf[j][q] = 0.f;

        #pragma unroll
        for (int t = 0; t < 4; t++) {
            uint32_t kf[8][2];
            #pragma unroll
            for (int g = 0; g < 4; g++) {
                uint32_t r4[4];
                ldsm_x4(r4, kbuf + (g * 16 + b_r) * AT_RB + t * 32 + b_c);
                kf[2*g][0] = r4[0]; kf[2*g][1] = r4[2];
                kf[2*g+1][0] = r4[1]; kf[2*g+1][1] = r4[3];
            }
            #pragma unroll
            for (int j = 0; j < 8; j++)
                mma_f16(sf[j], qf[t], kf[j]);
        }

        // ---- online softmax ----
        float tm0 = -1e30f, tm1 = -1e30f;
        #pragma unroll
        for (int j = 0; j < 8; j++) {
            tm0 = fmaxf(tm0, fmaxf(sf[j][0], sf[j][1]));
            tm1 = fmaxf(tm1, fmaxf(sf[j][2], sf[j][3]));
        }
        tm0 = fmaxf(tm0, __shfl_xor_sync(0xffffffffu, tm0, 1));
        tm0 = fmaxf(tm0, __shfl_xor_sync(0xffffffffu, tm0, 2));
        tm1 = fmaxf(tm1, __shfl_xor_sync(0xffffffffu, tm1, 1));
        tm1 = fmaxf(tm1, __shfl_xor_sync(0xffffffffu, tm1, 2));
        float mn0 = fmaxf(mrow0, tm0), mn1 = fmaxf(mrow1, tm1);
        float cor0 = __expf(mrow0 - mn0), cor1 = __expf(mrow1 - mn1);
        float rs0 = 0.f, rs1 = 0.f;
        #pragma unroll
        for (int j = 0; j < 8; j++) {
            sf[j][0] = __expf(sf[j][0] - mn0);
            sf[j][1] = __expf(sf[j][1] - mn0);
            sf[j][2] = __expf(sf[j][2] - mn1);
            sf[j][3] = __expf(sf[j][3] - mn1);
            rs0 += sf[j][0] + sf[j][1];
            rs1 += sf[j][2] + sf[j][3];
        }
        rs0 += __shfl_xor_sync(0xffffffffu, rs0, 1);
        rs0 += __shfl_xor_sync(0xffffffffu, rs0, 2);
        rs1 += __shfl_xor_sync(0xffffffffu, rs1, 1);
        rs1 += __shfl_xor_sync(0xffffffffu, rs1, 2);
        lrow0 = lrow0 * cor0 + rs0;
        lrow1 = lrow1 * cor1 + rs1;
        mrow0 = mn0; mrow1 = mn1;
        #pragma unroll
        for (int j = 0; j < 8; j++) {
            of[j][0] *= cor0; of[j][1] *= cor0;
            of[j][2] *= cor1; of[j][3] *= cor1;
        }

        // ---- P -> fp16 fragments ----
        uint32_t ph[4][4];
        #pragma unroll
        for (int t = 0; t < 4; t++) {
            #pragma unroll
            for (int half = 0; half < 2; half++) {
                const float* p2 = sf[2 * t + half];
                ph[t][2 * half + 0] = pack2h(p2[0], p2[1]);
                ph[t][2 * half + 1] = pack2h(p2[2], p2[3]);
            }
        }

        // ---- O += P V (fp16 1-term) ----
        #pragma unroll
        for (int t = 0; t < 4; t++) {
            uint32_t vf[8][2];
            #pragma unroll
            for (int g = 0; g < 4; g++) {
                uint32_t r4[4];
                ldsm_x4_t(r4, vbuf + (t * 16 + v_r) * AT_RB + g * 32 + v_c);
                vf[2*g][0] = r4[0]; vf[2*g][1] = r4[1];
                vf[2*g+1][0] = r4[2]; vf[2*g+1][1] = r4[3];
            }
            #pragma unroll
            for (int j = 0; j < 8; j++)
                mma_f16(of[j], ph[t], vf[j]);
        }
    }

    // ---- epilogue: fp16 out [B, S, H*Dk] ----
    const float inv0 = 1.f / lrow0, inv1 = 1.f / lrow1;
    const int r0 = q0 + wq + (lane >> 2), r1 = r0 + 8;
    const int b_ = bh >> 4, h_ = bh & 15;
    #pragma unroll
    for (int j = 0; j < 8; j++) {
        int d = j * 8 + (lane & 3) * 2;
        size_t i0 = ((size_t)b_ * SEQ + r0) * DMODEL + h_ * 64 + d;
        size_t i1 = ((size_t)b_ * SEQ + r1) * DMODEL + h_ * 64 + d;
        *(uint32_t*)(Ao + i0) = pack2h(of[j][0] * inv0, of[j][1] * inv0);
        *(uint32_t*)(Ao + i1) = pack2h(of[j][2] * inv1, of[j][3] * inv1);
    }
}

// ---------------------------------------------------------------------------
// Launch
// ---------------------------------------------------------------------------
extern "C" void kernel_launch(void* const* d_in, const int* in_sizes, int n_in,
                              void* d_out, int out_size)
{
    const float* x  = (const float*)d_in[0];
    const float* wq = (const float*)d_in[1];
    const float* bq = (const float*)d_in[2];
    const float* wk = (const float*)d_in[3];
    const float* bk = (const float*)d_in[4];
    const float* wv = (const float*)d_in[5];
    const float* bv = (const float*)d_in[6];
    const float* wo = (const float*)d_in[7];
    const float* bo = (const float*)d_in[8];
    float* out = (float*)d_out;

    __half *xh, *wt, *qkv, *aoh;
    float* bias3;
    cudaGetSymbolAddress((void**)&xh,    g_xh);
    cudaGetSymbolAddress((void**)&wt,    g_wt);
    cudaGetSymbolAddress((void**)&qkv,   g_qkv);
    cudaGetSymbolAddress((void**)&aoh,   g_aoh);
    cudaGetSymbolAddress((void**)&bias3, g_bias);

    cudaFuncSetAttribute(gemm_h,
                         cudaFuncAttributeMaxDynamicSharedMemorySize, G3_SMEM);
    cudaFuncSetAttribute(attn_mma,
                         cudaFuncAttributeMaxDynamicSharedMemorySize, AT_SMEM);

    // 1. prep
    int n4 = PSZ / 4;
    x_to_h<<<(n4 + 255) / 256, 256>>>(x, xh, n4);
    dim3 tgrid(DMODEL / 32, DMODEL / 32);
    wtrans_kernel<<<tgrid, 256>>>(wq, wt + 0 * WSZ);
    wtrans_kernel<<<tgrid, 256>>>(wk, wt + 1 * WSZ);
    wtrans_kernel<<<tgrid, 256>>>(wv, wt + 2 * WSZ);
    wtrans_kernel<<<tgrid, 256>>>(wo, wt + 3 * WSZ);
    bias_concat<<<(DMODEL + 255) / 256, 256>>>(bq, bk, bv, bias3);

    // 2. fused QKV projection (N=3072) -> fp16 q,k,v
    dim3 qkv_grid(3 * DMODEL / 256, MROWS / 128);   // (12, 64)
    gemm_h<<<qkv_grid, 256, G3_SMEM>>>(xh, wt, bias3, qkv, nullptr, 0);

    // 3. attention (all fp16)
    dim3 agrid(SEQ / 128, BATCH * HEADS);   // (16, 64)
    attn_mma<<<agrid, 256, AT_SMEM>>>(qkv, qkv + PSZ, qkv + 2 * PSZ, aoh);

    // 4. final projection (N=1024) -> fp32 out
    dim3 ogrid(DMODEL / 256, MROWS / 128);   // (4, 64)
    gemm_h<<<ogrid, 256, G3_SMEM>>>(aoh, wt + 3 * WSZ, bo, nullptr, out, 1);
}